// round 1
// baseline (speedup 1.0000x reference)
#include <cuda_runtime.h>
#include <cuda_bf16.h>
#include <math.h>

// Problem constants
#define NN    50000
#define EE    800000
#define INCH  128
#define HID   64
#define HEADS 4
#define ACT   5

// ---------------- scratch (device globals; no allocation allowed) ----------------
__device__ float g_h1[NN * HEADS * HID];     // x @ W1              [N,256]
__device__ float g_out1[NN * HEADS * HID];   // layer1 accum/output [N,256]
__device__ float g_asrc1[NN * HEADS];
__device__ float g_adst1[NN * HEADS];
__device__ float g_den1[NN * HEADS];
__device__ float g_g2[NN * HID];             // h @ W2              [N,64]
__device__ float g_out2[NN * HID];           // layer2 accum/output [N,64]
__device__ float g_asrc2[NN];
__device__ float g_adst2[NN];
__device__ float g_den2[NN];

// ---------------- helpers ----------------
__device__ __forceinline__ void red_add_v4(float* p, float4 v) {
    asm volatile("red.global.add.v4.f32 [%0], {%1,%2,%3,%4};"
                 :: "l"(p), "f"(v.x), "f"(v.y), "f"(v.z), "f"(v.w) : "memory");
}

__device__ __forceinline__ float lrelu(float x) {
    return x > 0.0f ? x : 0.2f * x;
}

// ---------------- zero scratch ----------------
__global__ void zero_scratch() {
    const int n1 = NN * HEADS * HID / 4;  // g_out1 float4s = 3,200,000
    const int n2 = NN * HID / 4;          // g_out2 float4s =   800,000
    const int n3 = NN * HEADS / 4;        // g_den1 float4s =    50,000
    const int n4 = NN / 4;                // g_den2 float4s =    12,500
    int i = blockIdx.x * blockDim.x + threadIdx.x;
    float4 z = make_float4(0.f, 0.f, 0.f, 0.f);
    if (i < n1) ((float4*)g_out1)[i] = z;
    if (i < n2) ((float4*)g_out2)[i] = z;
    if (i < n3) ((float4*)g_den1)[i] = z;
    if (i < n4) ((float4*)g_den2)[i] = z;
}

// ---------------- tiled SGEMM: C[M,N] = A[M,K] @ B[K,N] ----------------
// BM=128 BN=64 BK=16, 256 threads, 8x4 per-thread tile. N % 64 == 0, K % 16 == 0.
__global__ void sgemm(const float* __restrict__ A, const float* __restrict__ B,
                      float* __restrict__ C, int M, int N, int K) {
    const int BM = 128, BN = 64, BK = 16, TM = 8, TN = 4;
    __shared__ float As[BK][BM];
    __shared__ float Bs[BK][BN];
    int tid = threadIdx.x;
    int block_row = blockIdx.y * BM;
    int block_col = blockIdx.x * BN;
    int tr = (tid / (BN / TN)) * TM;   // 0..120
    int tc = (tid % (BN / TN)) * TN;   // 0..60
    float acc[TM][TN];
#pragma unroll
    for (int i = 0; i < TM; i++)
#pragma unroll
        for (int j = 0; j < TN; j++) acc[i][j] = 0.0f;

    for (int k0 = 0; k0 < K; k0 += BK) {
        // A tile: 128x16 = 512 float4, 2 per thread, store transposed
#pragma unroll
        for (int i = 0; i < 2; i++) {
            int idx = tid + i * 256;            // 0..511
            int row = idx >> 2;                 // 0..127
            int kq  = idx & 3;                  // 0..3
            int gr = block_row + row;
            float4 v = make_float4(0.f, 0.f, 0.f, 0.f);
            if (gr < M) v = *(const float4*)&A[(size_t)gr * K + k0 + kq * 4];
            As[kq * 4 + 0][row] = v.x;
            As[kq * 4 + 1][row] = v.y;
            As[kq * 4 + 2][row] = v.z;
            As[kq * 4 + 3][row] = v.w;
        }
        // B tile: 16x64 = 256 float4, 1 per thread
        {
            int kk = tid >> 4;       // 0..15
            int cq = tid & 15;       // 0..15
            float4 v = *(const float4*)&B[(size_t)(k0 + kk) * N + block_col + cq * 4];
            *(float4*)&Bs[kk][cq * 4] = v;
        }
        __syncthreads();
#pragma unroll
        for (int kk = 0; kk < BK; kk++) {
            float a[TM], b[TN];
#pragma unroll
            for (int i = 0; i < TM; i++) a[i] = As[kk][tr + i];
#pragma unroll
            for (int j = 0; j < TN; j++) b[j] = Bs[kk][tc + j];
#pragma unroll
            for (int i = 0; i < TM; i++)
#pragma unroll
                for (int j = 0; j < TN; j++) acc[i][j] += a[i] * b[j];
        }
        __syncthreads();
    }
#pragma unroll
    for (int i = 0; i < TM; i++) {
        int gr = block_row + tr + i;
        if (gr < M) {
            *(float4*)&C[(size_t)gr * N + block_col + tc] =
                make_float4(acc[i][0], acc[i][1], acc[i][2], acc[i][3]);
        }
    }
}

// ---------------- per-node attention logits, layer 1 (4 heads) ----------------
__global__ void alpha1_kernel(const float* __restrict__ a_src,
                              const float* __restrict__ a_dst) {
    int t = blockIdx.x * blockDim.x + threadIdx.x;
    if (t >= NN * HEADS) return;
    int n = t >> 2, h = t & 3;
    const float* hp = &g_h1[n * (HEADS * HID) + h * HID];
    const float* as = &a_src[h * HID];
    const float* ad = &a_dst[h * HID];
    float ss = 0.f, sd = 0.f;
#pragma unroll 8
    for (int c = 0; c < HID; c++) {
        float v = hp[c];
        ss += v * as[c];
        sd += v * ad[c];
    }
    g_asrc1[t] = ss;
    g_adst1[t] = sd;
}

// ---------------- per-node attention logits, layer 2 (1 head) ----------------
__global__ void alpha2_kernel(const float* __restrict__ a_src,
                              const float* __restrict__ a_dst) {
    int n = blockIdx.x * blockDim.x + threadIdx.x;
    if (n >= NN) return;
    const float* hp = &g_g2[n * HID];
    float ss = 0.f, sd = 0.f;
#pragma unroll 8
    for (int c = 0; c < HID; c++) {
        float v = hp[c];
        ss += v * a_src[c];
        sd += v * a_dst[c];
    }
    g_asrc2[n] = ss;
    g_adst2[n] = sd;
}

// ---------------- edge aggregation, layer 1 ----------------
// one thread per (edge, float4 of the 256-wide feature row)
__global__ void edge_aggr1(const int* __restrict__ ei, int E) {
    int t = blockIdx.x * blockDim.x + threadIdx.x;
    int ET = E + NN;
    if (t >= ET * 64) return;
    int e = t >> 6;
    int q = t & 63;            // float4 index 0..63
    int src, dst;
    if (e < E) { src = ei[e]; dst = ei[E + e]; }
    else       { src = dst = e - E; }
    int head = q >> 4;
    float s = g_asrc1[src * 4 + head] + g_adst1[dst * 4 + head];
    float p = __expf(lrelu(s));
    if ((q & 15) == 0) atomicAdd(&g_den1[dst * 4 + head], p);
    float4 hv = *(const float4*)&g_h1[src * 256 + q * 4];
    red_add_v4(&g_out1[dst * 256 + q * 4],
               make_float4(p * hv.x, p * hv.y, p * hv.z, p * hv.w));
}

// ---------------- edge aggregation, layer 2 ----------------
__global__ void edge_aggr2(const int* __restrict__ ei, int E) {
    int t = blockIdx.x * blockDim.x + threadIdx.x;
    int ET = E + NN;
    if (t >= ET * 16) return;
    int e = t >> 4;
    int q = t & 15;            // float4 index 0..15
    int src, dst;
    if (e < E) { src = ei[e]; dst = ei[E + e]; }
    else       { src = dst = e - E; }
    float s = g_asrc2[src] + g_adst2[dst];
    float p = __expf(lrelu(s));
    if (q == 0) atomicAdd(&g_den2[dst], p);
    float4 hv = *(const float4*)&g_g2[src * 64 + q * 4];
    red_add_v4(&g_out2[dst * 64 + q * 4],
               make_float4(p * hv.x, p * hv.y, p * hv.z, p * hv.w));
}

// ---------------- normalize + bias + relu, layer 1 ----------------
__global__ void norm1_kernel(const float* __restrict__ b1) {
    int i = blockIdx.x * blockDim.x + threadIdx.x;
    if (i >= NN * 256) return;
    int n = i >> 8, c = i & 255;
    int h = c >> 6;
    float v = g_out1[i] / (g_den1[n * 4 + h] + 1e-16f) + b1[c];
    g_out1[i] = v > 0.f ? v : 0.f;
}

// ---------------- normalize + bias + relu, layer 2 ----------------
__global__ void norm2_kernel(const float* __restrict__ b2) {
    int i = blockIdx.x * blockDim.x + threadIdx.x;
    if (i >= NN * 64) return;
    int n = i >> 6, c = i & 63;
    float v = g_out2[i] / (g_den2[n] + 1e-16f) + b2[c];
    g_out2[i] = v > 0.f ? v : 0.f;
}

// ---------------- final FC: out[N,5] = relu_h2 @ Wfc + bfc (warp per node) ----------------
__global__ void fc_kernel(const float* __restrict__ Wfc,
                          const float* __restrict__ bfc,
                          float* __restrict__ out) {
    int warp = (blockIdx.x * blockDim.x + threadIdx.x) >> 5;
    int lane = threadIdx.x & 31;
    if (warp >= NN) return;
    float acc[ACT];
#pragma unroll
    for (int a = 0; a < ACT; a++) acc[a] = 0.f;
#pragma unroll
    for (int cc = 0; cc < 2; cc++) {
        int c = lane + cc * 32;
        float v = g_out2[warp * 64 + c];
#pragma unroll
        for (int a = 0; a < ACT; a++) acc[a] += v * Wfc[c * ACT + a];
    }
#pragma unroll
    for (int a = 0; a < ACT; a++) {
#pragma unroll
        for (int o = 16; o > 0; o >>= 1)
            acc[a] += __shfl_down_sync(0xFFFFFFFFu, acc[a], o);
    }
    if (lane == 0) {
#pragma unroll
        for (int a = 0; a < ACT; a++)
            out[warp * ACT + a] = acc[a] + bfc[a];
    }
}

// ---------------- launch ----------------
extern "C" void kernel_launch(void* const* d_in, const int* in_sizes, int n_in,
                              void* d_out, int out_size) {
    const float* x      = (const float*)d_in[0];
    const int*   ei     = (const int*)  d_in[1];
    const float* W1     = (const float*)d_in[2];
    const float* a1_src = (const float*)d_in[3];
    const float* a1_dst = (const float*)d_in[4];
    const float* b1     = (const float*)d_in[5];
    const float* W2     = (const float*)d_in[6];
    const float* a2_src = (const float*)d_in[7];
    const float* a2_dst = (const float*)d_in[8];
    const float* b2     = (const float*)d_in[9];
    const float* Wfc    = (const float*)d_in[10];
    const float* bfc    = (const float*)d_in[11];
    float* out = (float*)d_out;

    int E = in_sizes[1] / 2;

    // device pointers to scratch (symbol refs happen inside kernels)
    float *p_h1, *p_out1, *p_g2;
    cudaGetSymbolAddress((void**)&p_h1,   g_h1);
    cudaGetSymbolAddress((void**)&p_out1, g_out1);
    cudaGetSymbolAddress((void**)&p_g2,   g_g2);

    // 0) zero accumulators
    {
        int n = NN * HEADS * HID / 4;
        zero_scratch<<<(n + 255) / 256, 256>>>();
    }
    // 1) h1 = x @ W1   [50000,128]x[128,256]
    {
        dim3 grid((HEADS * HID) / 64, (NN + 127) / 128);
        sgemm<<<grid, 256>>>(x, W1, p_h1, NN, HEADS * HID, INCH);
    }
    // 2) per-node logits layer1
    alpha1_kernel<<<(NN * HEADS + 255) / 256, 256>>>(a1_src, a1_dst);
    // 3) edge aggregation layer1
    {
        long long total = (long long)(E + NN) * 64;
        edge_aggr1<<<(unsigned)((total + 255) / 256), 256>>>(ei, E);
    }
    // 4) normalize + bias + relu
    norm1_kernel<<<(NN * 256 + 255) / 256, 256>>>(b1);
    // 5) g2 = h @ W2   [50000,256]x[256,64]
    {
        dim3 grid(HID / 64, (NN + 127) / 128);
        sgemm<<<grid, 256>>>(p_out1, W2, p_g2, NN, HID, HEADS * HID);
    }
    // 6) per-node logits layer2
    alpha2_kernel<<<(NN + 255) / 256, 256>>>(a2_src, a2_dst);
    // 7) edge aggregation layer2
    {
        long long total = (long long)(E + NN) * 16;
        edge_aggr2<<<(unsigned)((total + 255) / 256), 256>>>(ei, E);
    }
    // 8) normalize + bias + relu
    norm2_kernel<<<(NN * 64 + 255) / 256, 256>>>(b2);
    // 9) final FC
    fc_kernel<<<(NN * 32 + 255) / 256, 256>>>(Wfc, bfc, out);
}

// round 2
// speedup vs baseline: 1.3579x; 1.3579x over previous
#include <cuda_runtime.h>
#include <cuda_bf16.h>
#include <math.h>

#define NN    50000
#define EE    800000
#define INCH  128
#define HID   64
#define HEADS 4
#define ACT   5

// ---------------- scratch (device globals) ----------------
__device__ float g_h1[NN * HEADS * HID];     // x @ W1              [N,256]
__device__ float g_out1[NN * HEADS * HID];   // layer1 output       [N,256]
__device__ float g_asrc1[NN * HEADS];
__device__ float g_adst1[NN * HEADS];
__device__ float g_g2[NN * HID];             // h @ W2              [N,64]
__device__ float g_out2[NN * HID];           // layer2 output       [N,64]
__device__ float g_asrc2[NN];
__device__ float g_adst2[NN];
// CSR
__device__ int g_cnt[NN];
__device__ int g_off[NN + 1];
__device__ int g_pos[NN];
__device__ int g_csr[EE + NN];

__device__ __forceinline__ float lrelu(float x) {
    return x > 0.0f ? x : 0.2f * x;
}

// ---------------- CSR build ----------------
__global__ void init_cnt() {
    int i = blockIdx.x * blockDim.x + threadIdx.x;
    if (i < NN) g_cnt[i] = 1;   // self loop
}

__global__ void hist_kernel(const int* __restrict__ ei, int E) {
    int e = blockIdx.x * blockDim.x + threadIdx.x;
    if (e < E) atomicAdd(&g_cnt[ei[E + e]], 1);
}

// single-block exclusive scan over g_cnt -> g_off, g_pos
__global__ void scan_kernel() {
    __shared__ int ws[32];
    const int T = 1024;
    const int CH = (NN + T - 1) / T;     // 49
    int tid = threadIdx.x;
    int base = tid * CH;
    int local = 0;
    for (int j = 0; j < CH; j++) {
        int idx = base + j;
        if (idx < NN) local += g_cnt[idx];
    }
    int lane = tid & 31, wid = tid >> 5;
    int x = local;
#pragma unroll
    for (int o = 1; o < 32; o <<= 1) {
        int y = __shfl_up_sync(0xFFFFFFFFu, x, o);
        if (lane >= o) x += y;
    }
    if (lane == 31) ws[wid] = x;
    __syncthreads();
    if (wid == 0) {
        int w = ws[lane];
#pragma unroll
        for (int o = 1; o < 32; o <<= 1) {
            int y = __shfl_up_sync(0xFFFFFFFFu, w, o);
            if (lane >= o) w += y;
        }
        ws[lane] = w;
    }
    __syncthreads();
    int run = x - local + (wid > 0 ? ws[wid - 1] : 0);  // exclusive prefix
    for (int j = 0; j < CH; j++) {
        int idx = base + j;
        if (idx < NN) {
            g_off[idx] = run;
            g_pos[idx] = run;
            run += g_cnt[idx];
        }
    }
    if (tid == T - 1) g_off[NN] = run;
}

__global__ void scatter_kernel(const int* __restrict__ ei, int E) {
    int t = blockIdx.x * blockDim.x + threadIdx.x;
    int src, dst;
    if (t < E) { src = ei[t]; dst = ei[E + t]; }
    else if (t < E + NN) { src = dst = t - E; }
    else return;
    int pos = atomicAdd(&g_pos[dst], 1);
    g_csr[pos] = src;
}

// ---------------- SGEMM 128x128 tile, 8x8 per thread (for GEMM1) ----------------
__global__ void sgemm128(const float* __restrict__ A, const float* __restrict__ B,
                         float* __restrict__ C, int M, int N, int K) {
    __shared__ float As[8][128];
    __shared__ float Bs[8][128];
    int tid = threadIdx.x;
    int br = blockIdx.y * 128, bc = blockIdx.x * 128;
    int tr = (tid >> 4) * 8, tc = (tid & 15) * 8;
    float acc[8][8];
#pragma unroll
    for (int i = 0; i < 8; i++)
#pragma unroll
        for (int j = 0; j < 8; j++) acc[i][j] = 0.f;

    int arow = tid >> 1, akq = tid & 1;
    int bkk = tid >> 5, bcol = (tid & 31) * 4;

    for (int k0 = 0; k0 < K; k0 += 8) {
        int gr = br + arow;
        float4 v = make_float4(0.f, 0.f, 0.f, 0.f);
        if (gr < M) v = *(const float4*)&A[(size_t)gr * K + k0 + akq * 4];
        As[akq * 4 + 0][arow] = v.x;
        As[akq * 4 + 1][arow] = v.y;
        As[akq * 4 + 2][arow] = v.z;
        As[akq * 4 + 3][arow] = v.w;
        float4 w = *(const float4*)&B[(size_t)(k0 + bkk) * N + bc + bcol];
        *(float4*)&Bs[bkk][bcol] = w;
        __syncthreads();
#pragma unroll
        for (int kk = 0; kk < 8; kk++) {
            float a[8], b[8];
#pragma unroll
            for (int i = 0; i < 8; i++) a[i] = As[kk][tr + i];
#pragma unroll
            for (int j = 0; j < 8; j++) b[j] = Bs[kk][tc + j];
#pragma unroll
            for (int i = 0; i < 8; i++)
#pragma unroll
                for (int j = 0; j < 8; j++) acc[i][j] += a[i] * b[j];
        }
        __syncthreads();
    }
#pragma unroll
    for (int i = 0; i < 8; i++) {
        int gr = br + tr + i;
        if (gr < M) {
            *(float4*)&C[(size_t)gr * N + bc + tc] =
                make_float4(acc[i][0], acc[i][1], acc[i][2], acc[i][3]);
            *(float4*)&C[(size_t)gr * N + bc + tc + 4] =
                make_float4(acc[i][4], acc[i][5], acc[i][6], acc[i][7]);
        }
    }
}

// ---------------- SGEMM 128x64 tile, 8x4 per thread (for GEMM2) ----------------
__global__ void sgemm64(const float* __restrict__ A, const float* __restrict__ B,
                        float* __restrict__ C, int M, int N, int K) {
    const int BK = 16;
    __shared__ float As[BK][128];
    __shared__ float Bs[BK][64];
    int tid = threadIdx.x;
    int br = blockIdx.y * 128, bc = blockIdx.x * 64;
    int tr = (tid >> 4) * 8, tc = (tid & 15) * 4;
    float acc[8][4];
#pragma unroll
    for (int i = 0; i < 8; i++)
#pragma unroll
        for (int j = 0; j < 4; j++) acc[i][j] = 0.f;

    for (int k0 = 0; k0 < K; k0 += BK) {
#pragma unroll
        for (int i = 0; i < 2; i++) {
            int idx = tid + i * 256;
            int row = idx >> 2, kq = idx & 3;
            int gr = br + row;
            float4 v = make_float4(0.f, 0.f, 0.f, 0.f);
            if (gr < M) v = *(const float4*)&A[(size_t)gr * K + k0 + kq * 4];
            As[kq * 4 + 0][row] = v.x;
            As[kq * 4 + 1][row] = v.y;
            As[kq * 4 + 2][row] = v.z;
            As[kq * 4 + 3][row] = v.w;
        }
        {
            int kk = tid >> 4, cq = tid & 15;
            float4 v = *(const float4*)&B[(size_t)(k0 + kk) * N + bc + cq * 4];
            *(float4*)&Bs[kk][cq * 4] = v;
        }
        __syncthreads();
#pragma unroll
        for (int kk = 0; kk < BK; kk++) {
            float a[8], b[4];
#pragma unroll
            for (int i = 0; i < 8; i++) a[i] = As[kk][tr + i];
#pragma unroll
            for (int j = 0; j < 4; j++) b[j] = Bs[kk][tc + j];
#pragma unroll
            for (int i = 0; i < 8; i++)
#pragma unroll
                for (int j = 0; j < 4; j++) acc[i][j] += a[i] * b[j];
        }
        __syncthreads();
    }
#pragma unroll
    for (int i = 0; i < 8; i++) {
        int gr = br + tr + i;
        if (gr < M)
            *(float4*)&C[(size_t)gr * N + bc + tc] =
                make_float4(acc[i][0], acc[i][1], acc[i][2], acc[i][3]);
    }
}

// ---------------- per-node logits ----------------
__global__ void alpha1_kernel(const float* __restrict__ a_src,
                              const float* __restrict__ a_dst) {
    int t = blockIdx.x * blockDim.x + threadIdx.x;
    if (t >= NN * HEADS) return;
    int n = t >> 2, h = t & 3;
    const float* hp = &g_h1[n * (HEADS * HID) + h * HID];
    const float* as = &a_src[h * HID];
    const float* ad = &a_dst[h * HID];
    float ss = 0.f, sd = 0.f;
#pragma unroll 8
    for (int c = 0; c < HID; c++) {
        float v = hp[c];
        ss += v * as[c];
        sd += v * ad[c];
    }
    g_asrc1[t] = ss;
    g_adst1[t] = sd;
}

__global__ void alpha2_kernel(const float* __restrict__ a_src,
                              const float* __restrict__ a_dst) {
    int n = blockIdx.x * blockDim.x + threadIdx.x;
    if (n >= NN) return;
    const float* hp = &g_g2[n * HID];
    float ss = 0.f, sd = 0.f;
#pragma unroll 8
    for (int c = 0; c < HID; c++) {
        float v = hp[c];
        ss += v * a_src[c];
        sd += v * a_dst[c];
    }
    g_asrc2[n] = ss;
    g_adst2[n] = sd;
}

// ---------------- CSR aggregation, layer 1 (fused norm+bias+relu) ----------------
// 128 threads = 2 nodes per block, 64 threads (one float4 each) per node
__global__ void aggr1(const float* __restrict__ b1) {
    int node = blockIdx.x * 2 + (threadIdx.x >> 6);
    int c = threadIdx.x & 63;        // float4 index 0..63
    if (node >= NN) return;
    int h = c >> 4;
    float ad = g_adst1[node * 4 + h];
    int s0 = g_off[node], s1 = g_off[node + 1];
    float4 acc = make_float4(0.f, 0.f, 0.f, 0.f);
    float den = 0.f;
    int i = s0;
    for (; i + 1 < s1; i += 2) {
        int sa = g_csr[i], sb = g_csr[i + 1];
        float pa = __expf(lrelu(g_asrc1[sa * 4 + h] + ad));
        float pb = __expf(lrelu(g_asrc1[sb * 4 + h] + ad));
        float4 va = *(const float4*)&g_h1[sa * 256 + c * 4];
        float4 vb = *(const float4*)&g_h1[sb * 256 + c * 4];
        acc.x += pa * va.x + pb * vb.x;
        acc.y += pa * va.y + pb * vb.y;
        acc.z += pa * va.z + pb * vb.z;
        acc.w += pa * va.w + pb * vb.w;
        den += pa + pb;
    }
    if (i < s1) {
        int sa = g_csr[i];
        float pa = __expf(lrelu(g_asrc1[sa * 4 + h] + ad));
        float4 va = *(const float4*)&g_h1[sa * 256 + c * 4];
        acc.x += pa * va.x; acc.y += pa * va.y;
        acc.z += pa * va.z; acc.w += pa * va.w;
        den += pa;
    }
    float inv = 1.0f / (den + 1e-16f);
    float4 bb = *(const float4*)&b1[c * 4];
    float4 o;
    o.x = fmaxf(acc.x * inv + bb.x, 0.f);
    o.y = fmaxf(acc.y * inv + bb.y, 0.f);
    o.z = fmaxf(acc.z * inv + bb.z, 0.f);
    o.w = fmaxf(acc.w * inv + bb.w, 0.f);
    *(float4*)&g_out1[node * 256 + c * 4] = o;
}

// ---------------- CSR aggregation, layer 2 (warp per node, float2/thread) ----------------
__global__ void aggr2(const float* __restrict__ b2) {
    int node = blockIdx.x * 4 + (threadIdx.x >> 5);
    int lane = threadIdx.x & 31;
    if (node >= NN) return;
    float ad = g_adst2[node];
    int s0 = g_off[node], s1 = g_off[node + 1];
    float2 acc = make_float2(0.f, 0.f);
    float den = 0.f;
    int i = s0;
    for (; i + 1 < s1; i += 2) {
        int sa = g_csr[i], sb = g_csr[i + 1];
        float pa = __expf(lrelu(g_asrc2[sa] + ad));
        float pb = __expf(lrelu(g_asrc2[sb] + ad));
        float2 va = *(const float2*)&g_g2[sa * 64 + lane * 2];
        float2 vb = *(const float2*)&g_g2[sb * 64 + lane * 2];
        acc.x += pa * va.x + pb * vb.x;
        acc.y += pa * va.y + pb * vb.y;
        den += pa + pb;
    }
    if (i < s1) {
        int sa = g_csr[i];
        float pa = __expf(lrelu(g_asrc2[sa] + ad));
        float2 va = *(const float2*)&g_g2[sa * 64 + lane * 2];
        acc.x += pa * va.x;
        acc.y += pa * va.y;
        den += pa;
    }
    float inv = 1.0f / (den + 1e-16f);
    float2 bb = *(const float2*)&b2[lane * 2];
    float2 o;
    o.x = fmaxf(acc.x * inv + bb.x, 0.f);
    o.y = fmaxf(acc.y * inv + bb.y, 0.f);
    *(float2*)&g_out2[node * 64 + lane * 2] = o;
}

// ---------------- final FC ----------------
__global__ void fc_kernel(const float* __restrict__ Wfc,
                          const float* __restrict__ bfc,
                          float* __restrict__ out) {
    int warp = (blockIdx.x * blockDim.x + threadIdx.x) >> 5;
    int lane = threadIdx.x & 31;
    if (warp >= NN) return;
    float acc[ACT];
#pragma unroll
    for (int a = 0; a < ACT; a++) acc[a] = 0.f;
#pragma unroll
    for (int cc = 0; cc < 2; cc++) {
        int c = lane + cc * 32;
        float v = g_out2[warp * 64 + c];
#pragma unroll
        for (int a = 0; a < ACT; a++) acc[a] += v * Wfc[c * ACT + a];
    }
#pragma unroll
    for (int a = 0; a < ACT; a++) {
#pragma unroll
        for (int o = 16; o > 0; o >>= 1)
            acc[a] += __shfl_down_sync(0xFFFFFFFFu, acc[a], o);
    }
    if (lane == 0) {
#pragma unroll
        for (int a = 0; a < ACT; a++)
            out[warp * ACT + a] = acc[a] + bfc[a];
    }
}

// ---------------- launch ----------------
extern "C" void kernel_launch(void* const* d_in, const int* in_sizes, int n_in,
                              void* d_out, int out_size) {
    const float* x      = (const float*)d_in[0];
    const int*   ei     = (const int*)  d_in[1];
    const float* W1     = (const float*)d_in[2];
    const float* a1_src = (const float*)d_in[3];
    const float* a1_dst = (const float*)d_in[4];
    const float* b1     = (const float*)d_in[5];
    const float* W2     = (const float*)d_in[6];
    const float* a2_src = (const float*)d_in[7];
    const float* a2_dst = (const float*)d_in[8];
    const float* b2     = (const float*)d_in[9];
    const float* Wfc    = (const float*)d_in[10];
    const float* bfc    = (const float*)d_in[11];
    float* out = (float*)d_out;

    int E = in_sizes[1] / 2;

    float *p_h1, *p_out1, *p_g2;
    cudaGetSymbolAddress((void**)&p_h1,   g_h1);
    cudaGetSymbolAddress((void**)&p_out1, g_out1);
    cudaGetSymbolAddress((void**)&p_g2,   g_g2);

    // CSR build
    init_cnt<<<(NN + 255) / 256, 256>>>();
    hist_kernel<<<(E + 255) / 256, 256>>>(ei, E);
    scan_kernel<<<1, 1024>>>();
    scatter_kernel<<<(E + NN + 255) / 256, 256>>>(ei, E);

    // GEMM1: [50000,128] x [128,256]
    {
        dim3 grid((HEADS * HID) / 128, (NN + 127) / 128);
        sgemm128<<<grid, 256>>>(x, W1, p_h1, NN, HEADS * HID, INCH);
    }
    alpha1_kernel<<<(NN * HEADS + 255) / 256, 256>>>(a1_src, a1_dst);
    aggr1<<<(NN + 1) / 2, 128>>>(b1);

    // GEMM2: [50000,256] x [256,64]
    {
        dim3 grid(HID / 64, (NN + 127) / 128);
        sgemm64<<<grid, 256>>>(p_out1, W2, p_g2, NN, HID, HEADS * HID);
    }
    alpha2_kernel<<<(NN + 255) / 256, 256>>>(a2_src, a2_dst);
    aggr2<<<(NN + 3) / 4, 128>>>(b2);

    fc_kernel<<<(NN * 32 + 255) / 256, 256>>>(Wfc, bfc, out);
}

// round 3
// speedup vs baseline: 1.3926x; 1.0255x over previous
#include <cuda_runtime.h>
#include <cuda_bf16.h>
#include <math.h>

#define NN    50000
#define EE    800000
#define INCH  128
#define HID   64
#define HEADS 4
#define ACT   5

// ---------------- scratch ----------------
__device__ float g_agg1[NN * 4 * 128];   // per-head weighted x sums [N][4][128]
__device__ float g_out1[NN * 256];       // layer1 output
__device__ float g_asrc1[NN * 4];
__device__ float g_adst1[NN * 4];
__device__ float g_den1[NN * 4];
__device__ float g_g2[NN * 64];          // out1 @ W2
__device__ float g_out2[NN * 64];        // layer2 output
__device__ float g_asrc2[NN];
__device__ float g_adst2[NN];
__device__ float g_w1a[128 * 8];         // W1-projected attention vecs (j = h for src, 4+h for dst)
__device__ float g_w2a[256 * 2];
// CSR
__device__ int g_cnt[NN];
__device__ int g_off[NN + 1];
__device__ int g_pos[NN];
__device__ int g_csr[EE + NN];

__device__ __forceinline__ float lrelu(float x) { return x > 0.0f ? x : 0.2f * x; }

__device__ __forceinline__ unsigned f2tf32(float f) {
    unsigned u;
    asm("cvt.rna.tf32.f32 %0, %1;" : "=r"(u) : "f"(f));
    return u;
}

__device__ __forceinline__ void mma_tf32(float& d0, float& d1, float& d2, float& d3,
                                         unsigned a0, unsigned a1, unsigned a2, unsigned a3,
                                         unsigned b0, unsigned b1) {
    asm volatile("mma.sync.aligned.m16n8k8.row.col.f32.tf32.tf32.f32 "
                 "{%0,%1,%2,%3},{%4,%5,%6,%7},{%8,%9},{%0,%1,%2,%3};"
                 : "+f"(d0), "+f"(d1), "+f"(d2), "+f"(d3)
                 : "r"(a0), "r"(a1), "r"(a2), "r"(a3), "r"(b0), "r"(b1));
}

// ---------------- CSR build ----------------
__global__ void init_cnt() {
    int i = blockIdx.x * blockDim.x + threadIdx.x;
    if (i < NN) g_cnt[i] = 1;
}
__global__ void hist_kernel(const int* __restrict__ ei, int E) {
    int e = blockIdx.x * blockDim.x + threadIdx.x;
    if (e < E) atomicAdd(&g_cnt[ei[E + e]], 1);
}
__global__ void scan_kernel() {
    __shared__ int ws[32];
    const int T = 1024;
    const int CH = (NN + T - 1) / T;
    int tid = threadIdx.x;
    int base = tid * CH;
    int local = 0;
    for (int j = 0; j < CH; j++) { int idx = base + j; if (idx < NN) local += g_cnt[idx]; }
    int lane = tid & 31, wid = tid >> 5;
    int x = local;
#pragma unroll
    for (int o = 1; o < 32; o <<= 1) { int y = __shfl_up_sync(~0u, x, o); if (lane >= o) x += y; }
    if (lane == 31) ws[wid] = x;
    __syncthreads();
    if (wid == 0) {
        int w = ws[lane];
#pragma unroll
        for (int o = 1; o < 32; o <<= 1) { int y = __shfl_up_sync(~0u, w, o); if (lane >= o) w += y; }
        ws[lane] = w;
    }
    __syncthreads();
    int run = x - local + (wid > 0 ? ws[wid - 1] : 0);
    for (int j = 0; j < CH; j++) {
        int idx = base + j;
        if (idx < NN) { g_off[idx] = run; g_pos[idx] = run; run += g_cnt[idx]; }
    }
    if (tid == T - 1) g_off[NN] = run;
}
__global__ void scatter_kernel(const int* __restrict__ ei, int E) {
    int t = blockIdx.x * blockDim.x + threadIdx.x;
    int src, dst;
    if (t < E) { src = ei[t]; dst = ei[E + t]; }
    else if (t < E + NN) { src = dst = t - E; }
    else return;
    int pos = atomicAdd(&g_pos[dst], 1);
    g_csr[pos] = src;
}

// ---------------- attention-vector precompute ----------------
__global__ void w1a_pre(const float* __restrict__ W1, const float* __restrict__ a1s,
                        const float* __restrict__ a1d) {
    int t = blockIdx.x * blockDim.x + threadIdx.x;  // 128*8
    if (t >= 128 * 8) return;
    int k = t >> 3, j = t & 7;
    int h = j & 3;
    const float* av = (j < 4 ? a1s : a1d) + h * 64;
    const float* wr = W1 + (size_t)k * 256 + h * 64;
    float s = 0.f;
#pragma unroll 8
    for (int c = 0; c < 64; c++) s += wr[c] * av[c];
    g_w1a[k * 8 + j] = s;
}
__global__ void w2a_pre(const float* __restrict__ W2, const float* __restrict__ a2s,
                        const float* __restrict__ a2d) {
    int t = blockIdx.x * blockDim.x + threadIdx.x;  // 256*2
    if (t >= 256 * 2) return;
    int k = t >> 1, j = t & 1;
    const float* av = (j == 0 ? a2s : a2d);
    const float* wr = W2 + (size_t)k * 64;
    float s = 0.f;
#pragma unroll 8
    for (int c = 0; c < 64; c++) s += wr[c] * av[c];
    g_w2a[k * 2 + j] = s;
}

// ---------------- alpha1: [N,4] src/dst logits = x @ w1a ----------------
__global__ void alpha1_kernel(const float* __restrict__ x) {
    int node = blockIdx.x * 8 + (threadIdx.x >> 5);
    int lane = threadIdx.x & 31;
    if (node >= NN) return;
    float4 xv = *(const float4*)&x[(size_t)node * 128 + lane * 4];
    float s[8];
#pragma unroll
    for (int j = 0; j < 8; j++) s[j] = 0.f;
#pragma unroll
    for (int k = 0; k < 4; k++) {
        float xk = (&xv.x)[k];
        const float* wr = &g_w1a[(lane * 4 + k) * 8];
        float4 wa = *(const float4*)&wr[0];
        float4 wb = *(const float4*)&wr[4];
        s[0] += xk * wa.x; s[1] += xk * wa.y; s[2] += xk * wa.z; s[3] += xk * wa.w;
        s[4] += xk * wb.x; s[5] += xk * wb.y; s[6] += xk * wb.z; s[7] += xk * wb.w;
    }
#pragma unroll
    for (int j = 0; j < 8; j++) {
#pragma unroll
        for (int o = 16; o > 0; o >>= 1) s[j] += __shfl_xor_sync(~0u, s[j], o);
    }
    if (lane == 0) {
        *(float4*)&g_asrc1[node * 4] = make_float4(s[0], s[1], s[2], s[3]);
        *(float4*)&g_adst1[node * 4] = make_float4(s[4], s[5], s[6], s[7]);
    }
}

// ---------------- aggr1: per-head weighted x sums (warp per node) ----------------
__global__ void aggr1_kernel(const float* __restrict__ x) {
    int node = blockIdx.x * 8 + (threadIdx.x >> 5);
    int lane = threadIdx.x & 31;
    if (node >= NN) return;
    float4 ad = *(const float4*)&g_adst1[node * 4];
    int s0 = g_off[node], s1 = g_off[node + 1];
    float4 acc0 = make_float4(0,0,0,0), acc1 = acc0, acc2 = acc0, acc3 = acc0;
    float4 den = make_float4(0,0,0,0);
    int i = s0;
    for (; i + 1 < s1; i += 2) {
        int sa = g_csr[i], sb = g_csr[i + 1];
        float4 ea = *(const float4*)&g_asrc1[sa * 4];
        float4 eb = *(const float4*)&g_asrc1[sb * 4];
        float4 pa, pb;
        pa.x = __expf(lrelu(ea.x + ad.x)); pa.y = __expf(lrelu(ea.y + ad.y));
        pa.z = __expf(lrelu(ea.z + ad.z)); pa.w = __expf(lrelu(ea.w + ad.w));
        pb.x = __expf(lrelu(eb.x + ad.x)); pb.y = __expf(lrelu(eb.y + ad.y));
        pb.z = __expf(lrelu(eb.z + ad.z)); pb.w = __expf(lrelu(eb.w + ad.w));
        float4 xa = *(const float4*)&x[(size_t)sa * 128 + lane * 4];
        float4 xb = *(const float4*)&x[(size_t)sb * 128 + lane * 4];
        acc0.x += pa.x * xa.x + pb.x * xb.x; acc0.y += pa.x * xa.y + pb.x * xb.y;
        acc0.z += pa.x * xa.z + pb.x * xb.z; acc0.w += pa.x * xa.w + pb.x * xb.w;
        acc1.x += pa.y * xa.x + pb.y * xb.x; acc1.y += pa.y * xa.y + pb.y * xb.y;
        acc1.z += pa.y * xa.z + pb.y * xb.z; acc1.w += pa.y * xa.w + pb.y * xb.w;
        acc2.x += pa.z * xa.x + pb.z * xb.x; acc2.y += pa.z * xa.y + pb.z * xb.y;
        acc2.z += pa.z * xa.z + pb.z * xb.z; acc2.w += pa.z * xa.w + pb.z * xb.w;
        acc3.x += pa.w * xa.x + pb.w * xb.x; acc3.y += pa.w * xa.y + pb.w * xb.y;
        acc3.z += pa.w * xa.z + pb.w * xb.z; acc3.w += pa.w * xa.w + pb.w * xb.w;
        den.x += pa.x + pb.x; den.y += pa.y + pb.y;
        den.z += pa.z + pb.z; den.w += pa.w + pb.w;
    }
    if (i < s1) {
        int sa = g_csr[i];
        float4 ea = *(const float4*)&g_asrc1[sa * 4];
        float4 pa;
        pa.x = __expf(lrelu(ea.x + ad.x)); pa.y = __expf(lrelu(ea.y + ad.y));
        pa.z = __expf(lrelu(ea.z + ad.z)); pa.w = __expf(lrelu(ea.w + ad.w));
        float4 xa = *(const float4*)&x[(size_t)sa * 128 + lane * 4];
        acc0.x += pa.x * xa.x; acc0.y += pa.x * xa.y; acc0.z += pa.x * xa.z; acc0.w += pa.x * xa.w;
        acc1.x += pa.y * xa.x; acc1.y += pa.y * xa.y; acc1.z += pa.y * xa.z; acc1.w += pa.y * xa.w;
        acc2.x += pa.z * xa.x; acc2.y += pa.z * xa.y; acc2.z += pa.z * xa.z; acc2.w += pa.z * xa.w;
        acc3.x += pa.w * xa.x; acc3.y += pa.w * xa.y; acc3.z += pa.w * xa.z; acc3.w += pa.w * xa.w;
        den.x += pa.x; den.y += pa.y; den.z += pa.z; den.w += pa.w;
    }
    size_t base = (size_t)node * 512 + lane * 4;
    *(float4*)&g_agg1[base]       = acc0;
    *(float4*)&g_agg1[base + 128] = acc1;
    *(float4*)&g_agg1[base + 256] = acc2;
    *(float4*)&g_agg1[base + 384] = acc3;
    if (lane == 0) *(float4*)&g_den1[node * 4] = den;
}

// ---------------- tf32 tensor-core GEMM: C[M,64] = A[M,K] @ B[K,64] ----------------
// block 256 thr, tile 128x64, BK=32; blockIdx.z selects head slice via za/zb/zc.
// If den != null: C = relu(acc / (den[row*4+z]+eps) + bias[zc*z + col]).
__global__ void gemm_tf32(const float* __restrict__ A, int lda, int za,
                          const float* __restrict__ B, int ldb, int zb,
                          float* __restrict__ C, int ldc, int zc,
                          int M, int K,
                          const float* __restrict__ den,
                          const float* __restrict__ bias) {
    __shared__ unsigned As[128][36];
    __shared__ unsigned Bs[32][72];
    int tid = threadIdx.x;
    int lane = tid & 31, wid = tid >> 5;
    int wm = wid >> 1, wn = wid & 1;          // 4x2 warp grid
    int z = blockIdx.z;
    int br = blockIdx.y * 128;
    const float* Ab = A + (size_t)z * za;
    const float* Bb = B + (size_t)z * zb;

    float acc[2][4][4];
#pragma unroll
    for (int mt = 0; mt < 2; mt++)
#pragma unroll
        for (int nt = 0; nt < 4; nt++)
#pragma unroll
            for (int r = 0; r < 4; r++) acc[mt][nt][r] = 0.f;

    for (int k0 = 0; k0 < K; k0 += 32) {
#pragma unroll
        for (int i = 0; i < 4; i++) {
            int id = tid + i * 256;          // 0..1023
            int row = id >> 3, kq = id & 7;
            int gr = br + row;
            float4 v = make_float4(0,0,0,0);
            if (gr < M) v = *(const float4*)&Ab[(size_t)gr * lda + k0 + kq * 4];
            As[row][kq * 4 + 0] = f2tf32(v.x);
            As[row][kq * 4 + 1] = f2tf32(v.y);
            As[row][kq * 4 + 2] = f2tf32(v.z);
            As[row][kq * 4 + 3] = f2tf32(v.w);
        }
#pragma unroll
        for (int i = 0; i < 2; i++) {
            int id = tid + i * 256;          // 0..511
            int kr = id >> 4, cq = id & 15;
            float4 v = *(const float4*)&Bb[(size_t)(k0 + kr) * ldb + cq * 4];
            Bs[kr][cq * 4 + 0] = f2tf32(v.x);
            Bs[kr][cq * 4 + 1] = f2tf32(v.y);
            Bs[kr][cq * 4 + 2] = f2tf32(v.z);
            Bs[kr][cq * 4 + 3] = f2tf32(v.w);
        }
        __syncthreads();
#pragma unroll
        for (int kk = 0; kk < 32; kk += 8) {
            unsigned af[2][4];
#pragma unroll
            for (int mt = 0; mt < 2; mt++) {
                int rb = wm * 32 + mt * 16 + (lane >> 2);
                af[mt][0] = As[rb][kk + (lane & 3)];
                af[mt][1] = As[rb + 8][kk + (lane & 3)];
                af[mt][2] = As[rb][kk + 4 + (lane & 3)];
                af[mt][3] = As[rb + 8][kk + 4 + (lane & 3)];
            }
            unsigned bf[4][2];
#pragma unroll
            for (int nt = 0; nt < 4; nt++) {
                int cb = wn * 32 + nt * 8 + (lane >> 2);
                bf[nt][0] = Bs[kk + (lane & 3)][cb];
                bf[nt][1] = Bs[kk + 4 + (lane & 3)][cb];
            }
#pragma unroll
            for (int mt = 0; mt < 2; mt++)
#pragma unroll
                for (int nt = 0; nt < 4; nt++)
                    mma_tf32(acc[mt][nt][0], acc[mt][nt][1], acc[mt][nt][2], acc[mt][nt][3],
                             af[mt][0], af[mt][1], af[mt][2], af[mt][3],
                             bf[nt][0], bf[nt][1]);
        }
        __syncthreads();
    }

    // epilogue
#pragma unroll
    for (int mt = 0; mt < 2; mt++) {
        int row0 = br + wm * 32 + mt * 16 + (lane >> 2);
#pragma unroll
        for (int half = 0; half < 2; half++) {
            int row = row0 + half * 8;
            if (row >= M) continue;
            float inv = 1.f, scale_on = 0.f;
            if (den) { inv = 1.0f / (den[row * 4 + z] + 1e-16f); scale_on = 1.f; }
#pragma unroll
            for (int nt = 0; nt < 4; nt++) {
                int col = wn * 32 + nt * 8 + 2 * (lane & 3);
                int gc = z * zc + col;
                float v0 = acc[mt][nt][half * 2 + 0];
                float v1 = acc[mt][nt][half * 2 + 1];
                if (scale_on != 0.f) {
                    v0 = fmaxf(v0 * inv + bias[gc], 0.f);
                    v1 = fmaxf(v1 * inv + bias[gc + 1], 0.f);
                }
                *(float2*)&C[(size_t)row * ldc + gc] = make_float2(v0, v1);
            }
        }
    }
}

// ---------------- alpha2: [N] logits = out1 @ w2a ----------------
__global__ void alpha2_kernel() {
    int node = blockIdx.x * 8 + (threadIdx.x >> 5);
    int lane = threadIdx.x & 31;
    if (node >= NN) return;
    float ss = 0.f, sd = 0.f;
#pragma unroll
    for (int q = 0; q < 2; q++) {
        float4 v = *(const float4*)&g_out1[(size_t)node * 256 + lane * 8 + q * 4];
#pragma unroll
        for (int k = 0; k < 4; k++) {
            int r = lane * 8 + q * 4 + k;
            float vk = (&v.x)[k];
            ss += vk * g_w2a[r * 2];
            sd += vk * g_w2a[r * 2 + 1];
        }
    }
#pragma unroll
    for (int o = 16; o > 0; o >>= 1) {
        ss += __shfl_xor_sync(~0u, ss, o);
        sd += __shfl_xor_sync(~0u, sd, o);
    }
    if (lane == 0) { g_asrc2[node] = ss; g_adst2[node] = sd; }
}

// ---------------- aggr2: gather g2, fused norm+bias+relu ----------------
__global__ void aggr2_kernel(const float* __restrict__ b2) {
    int node = blockIdx.x * 8 + (threadIdx.x >> 5);
    int lane = threadIdx.x & 31;
    if (node >= NN) return;
    float ad = g_adst2[node];
    int s0 = g_off[node], s1 = g_off[node + 1];
    float2 acc = make_float2(0.f, 0.f);
    float den = 0.f;
    int i = s0;
    for (; i + 1 < s1; i += 2) {
        int sa = g_csr[i], sb = g_csr[i + 1];
        float pa = __expf(lrelu(g_asrc2[sa] + ad));
        float pb = __expf(lrelu(g_asrc2[sb] + ad));
        float2 va = *(const float2*)&g_g2[(size_t)sa * 64 + lane * 2];
        float2 vb = *(const float2*)&g_g2[(size_t)sb * 64 + lane * 2];
        acc.x += pa * va.x + pb * vb.x;
        acc.y += pa * va.y + pb * vb.y;
        den += pa + pb;
    }
    if (i < s1) {
        int sa = g_csr[i];
        float pa = __expf(lrelu(g_asrc2[sa] + ad));
        float2 va = *(const float2*)&g_g2[(size_t)sa * 64 + lane * 2];
        acc.x += pa * va.x;
        acc.y += pa * va.y;
        den += pa;
    }
    float inv = 1.0f / (den + 1e-16f);
    float2 bb = *(const float2*)&b2[lane * 2];
    float2 o;
    o.x = fmaxf(acc.x * inv + bb.x, 0.f);
    o.y = fmaxf(acc.y * inv + bb.y, 0.f);
    *(float2*)&g_out2[(size_t)node * 64 + lane * 2] = o;
}

// ---------------- final FC ----------------
__global__ void fc_kernel(const float* __restrict__ Wfc,
                          const float* __restrict__ bfc,
                          float* __restrict__ out) {
    int warp = (blockIdx.x * blockDim.x + threadIdx.x) >> 5;
    int lane = threadIdx.x & 31;
    if (warp >= NN) return;
    float acc[ACT];
#pragma unroll
    for (int a = 0; a < ACT; a++) acc[a] = 0.f;
#pragma unroll
    for (int cc = 0; cc < 2; cc++) {
        int c = lane + cc * 32;
        float v = g_out2[(size_t)warp * 64 + c];
#pragma unroll
        for (int a = 0; a < ACT; a++) acc[a] += v * Wfc[c * ACT + a];
    }
#pragma unroll
    for (int a = 0; a < ACT; a++) {
#pragma unroll
        for (int o = 16; o > 0; o >>= 1)
            acc[a] += __shfl_down_sync(~0u, acc[a], o);
    }
    if (lane == 0) {
#pragma unroll
        for (int a = 0; a < ACT; a++)
            out[warp * ACT + a] = acc[a] + bfc[a];
    }
}

// ---------------- launch ----------------
extern "C" void kernel_launch(void* const* d_in, const int* in_sizes, int n_in,
                              void* d_out, int out_size) {
    const float* x      = (const float*)d_in[0];
    const int*   ei     = (const int*)  d_in[1];
    const float* W1     = (const float*)d_in[2];
    const float* a1_src = (const float*)d_in[3];
    const float* a1_dst = (const float*)d_in[4];
    const float* b1     = (const float*)d_in[5];
    const float* W2     = (const float*)d_in[6];
    const float* a2_src = (const float*)d_in[7];
    const float* a2_dst = (const float*)d_in[8];
    const float* b2     = (const float*)d_in[9];
    const float* Wfc    = (const float*)d_in[10];
    const float* bfc    = (const float*)d_in[11];
    float* out = (float*)d_out;

    int E = in_sizes[1] / 2;

    float *p_agg1, *p_out1, *p_g2, *p_den1;
    cudaGetSymbolAddress((void**)&p_agg1, g_agg1);
    cudaGetSymbolAddress((void**)&p_out1, g_out1);
    cudaGetSymbolAddress((void**)&p_g2,   g_g2);
    cudaGetSymbolAddress((void**)&p_den1, g_den1);

    // CSR build
    init_cnt<<<(NN + 255) / 256, 256>>>();
    hist_kernel<<<(E + 255) / 256, 256>>>(ei, E);
    scan_kernel<<<1, 1024>>>();
    scatter_kernel<<<(E + NN + 255) / 256, 256>>>(ei, E);

    // attention-vector precompute + layer1 logits
    w1a_pre<<<4, 256>>>(W1, a1_src, a1_dst);
    w2a_pre<<<2, 256>>>(W2, a2_src, a2_dst);
    alpha1_kernel<<<(NN + 7) / 8, 256>>>(x);

    // layer1: pre-GEMM aggregation, then head-blocked tf32 GEMM w/ fused epilogue
    aggr1_kernel<<<(NN + 7) / 8, 256>>>(x);
    {
        dim3 grid(1, (NN + 127) / 128, HEADS);
        gemm_tf32<<<grid, 256>>>(p_agg1, 512, 128,   // A = agg1 (head stride 128)
                                 W1, 256, 64,        // B = W1 (head col offset 64)
                                 p_out1, 256, 64,    // C = out1 (head col offset 64)
                                 NN, 128, p_den1, b1);
    }

    // layer2: g2 = out1 @ W2 (tf32), logits, gather, fused epilogue
    {
        dim3 grid(1, (NN + 127) / 128, 1);
        gemm_tf32<<<grid, 256>>>(p_out1, 256, 0,
                                 W2, 64, 0,
                                 p_g2, 64, 0,
                                 NN, 256, nullptr, nullptr);
    }
    alpha2_kernel<<<(NN + 7) / 8, 256>>>();
    aggr2_kernel<<<(NN + 7) / 8, 256>>>(b2);

    fc_kernel<<<(NN * 32 + 255) / 256, 256>>>(Wfc, bfc, out);
}

// round 5
// speedup vs baseline: 1.7078x; 1.2264x over previous
#include <cuda_runtime.h>
#include <cuda_bf16.h>
#include <math.h>

#define NN    50000
#define EE    800000
#define INCH  128
#define HID   64
#define HEADS 4
#define ACT   5

// ---------------- scratch ----------------
__device__ float g_out1[NN * 256];
__device__ float g_asrc1[NN * 4];
__device__ float g_adst1[NN * 4];
__device__ float g_g2[NN * 64];
__device__ float g_asrc2[NN];
__device__ float g_adst2[NN];
__device__ float g_w1a[128 * 8];
__device__ int   g_cnt[NN];          // zero-initialized; re-zeroed by scan each run
__device__ int   g_off[NN + 1];
__device__ int   g_pos[NN];
__device__ int   g_csr[EE + NN];
__device__ float g_p[(EE + NN) * 4]; // per-CSR-slot softmax weights (4 heads)

__device__ __forceinline__ float lrelu(float x) { return x > 0.0f ? x : 0.2f * x; }

__device__ __forceinline__ unsigned f2tf32(float f) {
    unsigned u;
    asm("cvt.rna.tf32.f32 %0, %1;" : "=r"(u) : "f"(f));
    return u;
}

__device__ __forceinline__ void mma_tf32(float& d0, float& d1, float& d2, float& d3,
                                         unsigned a0, unsigned a1, unsigned a2, unsigned a3,
                                         unsigned b0, unsigned b1) {
    asm volatile("mma.sync.aligned.m16n8k8.row.col.f32.tf32.tf32.f32 "
                 "{%0,%1,%2,%3},{%4,%5,%6,%7},{%8,%9},{%0,%1,%2,%3};"
                 : "+f"(d0), "+f"(d1), "+f"(d2), "+f"(d3)
                 : "r"(a0), "r"(a1), "r"(a2), "r"(a3), "r"(b0), "r"(b1));
}

// ============ K0: histogram (dst counts) + w1a precompute ============
__global__ void hist_wpre(const int* __restrict__ ei, int E, int histB,
                          const float* __restrict__ W1,
                          const float* __restrict__ a1s,
                          const float* __restrict__ a1d) {
    if ((int)blockIdx.x < histB) {
        int e = blockIdx.x * 256 + threadIdx.x;
        if (e < E) atomicAdd(&g_cnt[ei[E + e]], 1);
    } else {
        int t = (blockIdx.x - histB) * 256 + threadIdx.x;   // 0..1023
        if (t < 1024) {
            int k = t >> 3, j = t & 7, h = j & 3;
            const float* av = (j < 4 ? a1s : a1d) + h * 64;
            const float* wr = W1 + (size_t)k * 256 + h * 64;
            float s = 0.f;
#pragma unroll 8
            for (int c = 0; c < 64; c++) s += wr[c] * av[c];
            g_w1a[k * 8 + j] = s;
        }
    }
}

// ============ K1: block0 = exclusive scan (cnt+1 self-loop, re-zero cnt); others = alpha1 ============
__global__ void __launch_bounds__(1024) scan_alpha(const float* __restrict__ x) {
    __shared__ float w1s[128 * 8];
    if (blockIdx.x == 0) {
        __shared__ int ws[32];
        const int T = 1024;
        const int CH = (NN + T - 1) / T;
        int tid = threadIdx.x;
        int base = tid * CH;
        int cnts[49];
        int local = 0;
        for (int j = 0; j < CH; j++) {
            int idx = base + j;
            int c = 0;
            if (idx < NN) { c = g_cnt[idx] + 1; g_cnt[idx] = 0; }
            cnts[j] = c;
            local += c;
        }
        int lane = tid & 31, wid = tid >> 5;
        int v = local;
#pragma unroll
        for (int o = 1; o < 32; o <<= 1) { int y = __shfl_up_sync(~0u, v, o); if (lane >= o) v += y; }
        if (lane == 31) ws[wid] = v;
        __syncthreads();
        if (wid == 0) {
            int w = ws[lane];
#pragma unroll
            for (int o = 1; o < 32; o <<= 1) { int y = __shfl_up_sync(~0u, w, o); if (lane >= o) w += y; }
            ws[lane] = w;
        }
        __syncthreads();
        int run = v - local + (wid > 0 ? ws[wid - 1] : 0);
        for (int j = 0; j < CH; j++) {
            int idx = base + j;
            if (idx < NN) {
                g_off[idx] = run;
                g_pos[idx] = run;
                run += cnts[j];
            }
        }
        if (tid == T - 1) g_off[NN] = run;
    } else {
        int tid = threadIdx.x;
        if (tid < 1024) w1s[tid] = g_w1a[tid];
        __syncthreads();
        int wid = tid >> 5, lane = tid & 31;
        int node = (blockIdx.x - 1) * 32 + wid;
        if (node >= NN) return;
        float4 xv = *(const float4*)&x[(size_t)node * 128 + lane * 4];
        float s[8];
#pragma unroll
        for (int j = 0; j < 8; j++) s[j] = 0.f;
#pragma unroll
        for (int k = 0; k < 4; k++) {
            float xk = (&xv.x)[k];
            const float* wr = &w1s[(lane * 4 + k) * 8];
            float4 wa = *(const float4*)&wr[0];
            float4 wb = *(const float4*)&wr[4];
            s[0] += xk * wa.x; s[1] += xk * wa.y; s[2] += xk * wa.z; s[3] += xk * wa.w;
            s[4] += xk * wb.x; s[5] += xk * wb.y; s[6] += xk * wb.z; s[7] += xk * wb.w;
        }
#pragma unroll
        for (int j = 0; j < 8; j++) {
#pragma unroll
            for (int o = 16; o > 0; o >>= 1) s[j] += __shfl_xor_sync(~0u, s[j], o);
        }
        if (lane == 0) {
            *(float4*)&g_asrc1[node * 4] = make_float4(s[0], s[1], s[2], s[3]);
            *(float4*)&g_adst1[node * 4] = make_float4(s[4], s[5], s[6], s[7]);
        }
    }
}

// ============ K2: scatter src ids into CSR + precompute per-slot softmax weights ============
__global__ void scatter_p(const int* __restrict__ ei, int E) {
    int t = blockIdx.x * blockDim.x + threadIdx.x;
    int src, dst;
    if (t < E) { src = ei[t]; dst = ei[E + t]; }
    else if (t < E + NN) { src = dst = t - E; }
    else return;
    int pos = atomicAdd(&g_pos[dst], 1);
    g_csr[pos] = src;
    float4 es = *(const float4*)&g_asrc1[src * 4];
    float4 ed = *(const float4*)&g_adst1[dst * 4];
    float4 p;
    p.x = __expf(lrelu(es.x + ed.x));
    p.y = __expf(lrelu(es.y + ed.y));
    p.z = __expf(lrelu(es.z + ed.z));
    p.w = __expf(lrelu(es.w + ed.w));
    *(float4*)&g_p[(size_t)pos * 4] = p;
}

// ============ K3: fused gather-aggregate + tf32 GEMM1 + norm/bias/relu ============
// 32 nodes/block, 256 threads. smem: As[4][32][132] (tf32 bits), Bs[32][260], dens[32][4]
#define L1_SMEM ((4 * 32 * 132 + 32 * 260 + 128) * 4)
__global__ void __launch_bounds__(256) layer1_fused(const float* __restrict__ x,
                                                    const float* __restrict__ W1,
                                                    const float* __restrict__ b1) {
    extern __shared__ float sm[];
    float* As = sm;                       // 4*32*132
    float* Bs = sm + 4 * 32 * 132;        // 32*260
    float* dens = Bs + 32 * 260;          // 32*4
    int tid = threadIdx.x, lane = tid & 31, wid = tid >> 5;
    int node0 = blockIdx.x * 32;

    // ---- phase 1: gather Σ p_h · x[src] per head into smem (tf32-converted) ----
    for (int nl = wid; nl < 32; nl += 8) {
        int node = node0 + nl;
        float4 a0 = make_float4(0,0,0,0), a1 = a0, a2 = a0, a3 = a0;
        float4 dn = a0;
        if (node < NN) {
            int s0 = g_off[node], s1 = g_off[node + 1];
            int i = s0;
            for (; i + 1 < s1; i += 2) {
                int sa = g_csr[i], sb = g_csr[i + 1];
                float4 pa = *(const float4*)&g_p[(size_t)i * 4];
                float4 pb = *(const float4*)&g_p[(size_t)(i + 1) * 4];
                float4 xa = *(const float4*)&x[(size_t)sa * 128 + lane * 4];
                float4 xb = *(const float4*)&x[(size_t)sb * 128 + lane * 4];
                a0.x += pa.x * xa.x + pb.x * xb.x; a0.y += pa.x * xa.y + pb.x * xb.y;
                a0.z += pa.x * xa.z + pb.x * xb.z; a0.w += pa.x * xa.w + pb.x * xb.w;
                a1.x += pa.y * xa.x + pb.y * xb.x; a1.y += pa.y * xa.y + pb.y * xb.y;
                a1.z += pa.y * xa.z + pb.y * xb.z; a1.w += pa.y * xa.w + pb.y * xb.w;
                a2.x += pa.z * xa.x + pb.z * xb.x; a2.y += pa.z * xa.y + pb.z * xb.y;
                a2.z += pa.z * xa.z + pb.z * xb.z; a2.w += pa.z * xa.w + pb.z * xb.w;
                a3.x += pa.w * xa.x + pb.w * xb.x; a3.y += pa.w * xa.y + pb.w * xb.y;
                a3.z += pa.w * xa.z + pb.w * xb.z; a3.w += pa.w * xa.w + pb.w * xb.w;
                dn.x += pa.x + pb.x; dn.y += pa.y + pb.y;
                dn.z += pa.z + pb.z; dn.w += pa.w + pb.w;
            }
            if (i < s1) {
                int sa = g_csr[i];
                float4 pa = *(const float4*)&g_p[(size_t)i * 4];
                float4 xa = *(const float4*)&x[(size_t)sa * 128 + lane * 4];
                a0.x += pa.x * xa.x; a0.y += pa.x * xa.y; a0.z += pa.x * xa.z; a0.w += pa.x * xa.w;
                a1.x += pa.y * xa.x; a1.y += pa.y * xa.y; a1.z += pa.y * xa.z; a1.w += pa.y * xa.w;
                a2.x += pa.z * xa.x; a2.y += pa.z * xa.y; a2.z += pa.z * xa.z; a2.w += pa.z * xa.w;
                a3.x += pa.w * xa.x; a3.y += pa.w * xa.y; a3.z += pa.w * xa.z; a3.w += pa.w * xa.w;
                dn.x += pa.x; dn.y += pa.y; dn.z += pa.z; dn.w += pa.w;
            }
        }
        // store tf32-converted
        float4 c0, c1, c2, c3;
        c0.x = __uint_as_float(f2tf32(a0.x)); c0.y = __uint_as_float(f2tf32(a0.y));
        c0.z = __uint_as_float(f2tf32(a0.z)); c0.w = __uint_as_float(f2tf32(a0.w));
        c1.x = __uint_as_float(f2tf32(a1.x)); c1.y = __uint_as_float(f2tf32(a1.y));
        c1.z = __uint_as_float(f2tf32(a1.z)); c1.w = __uint_as_float(f2tf32(a1.w));
        c2.x = __uint_as_float(f2tf32(a2.x)); c2.y = __uint_as_float(f2tf32(a2.y));
        c2.z = __uint_as_float(f2tf32(a2.z)); c2.w = __uint_as_float(f2tf32(a2.w));
        c3.x = __uint_as_float(f2tf32(a3.x)); c3.y = __uint_as_float(f2tf32(a3.y));
        c3.z = __uint_as_float(f2tf32(a3.z)); c3.w = __uint_as_float(f2tf32(a3.w));
        *(float4*)&As[(0 * 32 + nl) * 132 + lane * 4] = c0;
        *(float4*)&As[(1 * 32 + nl) * 132 + lane * 4] = c1;
        *(float4*)&As[(2 * 32 + nl) * 132 + lane * 4] = c2;
        *(float4*)&As[(3 * 32 + nl) * 132 + lane * 4] = c3;
        if (lane == 0) {
            dens[nl * 4 + 0] = dn.x; dens[nl * 4 + 1] = dn.y;
            dens[nl * 4 + 2] = dn.z; dens[nl * 4 + 3] = dn.w;
        }
    }
    __syncthreads();

    // ---- phase 2: C[32,256] = A_h[32,128] @ W1[:, h*64:(h+1)*64], warp wn = head ----
    int wm = wid >> 2, wn = wid & 3;
    float acc[8][4];
#pragma unroll
    for (int nt = 0; nt < 8; nt++)
#pragma unroll
        for (int r = 0; r < 4; r++) acc[nt][r] = 0.f;

    for (int kc = 0; kc < 4; kc++) {
#pragma unroll
        for (int i = 0; i < 8; i++) {
            int id = tid + i * 256;          // 0..2047
            int kr = id >> 6, cq = id & 63;
            float4 v = *(const float4*)&W1[(size_t)(kc * 32 + kr) * 256 + cq * 4];
            Bs[kr * 260 + cq * 4 + 0] = __uint_as_float(f2tf32(v.x));
            Bs[kr * 260 + cq * 4 + 1] = __uint_as_float(f2tf32(v.y));
            Bs[kr * 260 + cq * 4 + 2] = __uint_as_float(f2tf32(v.z));
            Bs[kr * 260 + cq * 4 + 3] = __uint_as_float(f2tf32(v.w));
        }
        __syncthreads();
#pragma unroll
        for (int kk = 0; kk < 32; kk += 8) {
            int k0 = kc * 32 + kk;
            int ar = wm * 16 + (lane >> 2);
            unsigned a0 = __float_as_uint(As[(wn * 32 + ar) * 132 + k0 + (lane & 3)]);
            unsigned a1 = __float_as_uint(As[(wn * 32 + ar + 8) * 132 + k0 + (lane & 3)]);
            unsigned a2 = __float_as_uint(As[(wn * 32 + ar) * 132 + k0 + 4 + (lane & 3)]);
            unsigned a3 = __float_as_uint(As[(wn * 32 + ar + 8) * 132 + k0 + 4 + (lane & 3)]);
#pragma unroll
            for (int nt = 0; nt < 8; nt++) {
                int cb = wn * 64 + nt * 8 + (lane >> 2);
                unsigned b0 = __float_as_uint(Bs[(kk + (lane & 3)) * 260 + cb]);
                unsigned b1v = __float_as_uint(Bs[(kk + 4 + (lane & 3)) * 260 + cb]);
                mma_tf32(acc[nt][0], acc[nt][1], acc[nt][2], acc[nt][3],
                         a0, a1, a2, a3, b0, b1v);
            }
        }
        __syncthreads();
    }

    // ---- epilogue: normalize + bias + relu ----
#pragma unroll
    for (int nt = 0; nt < 8; nt++) {
        int col = wn * 64 + nt * 8 + 2 * (lane & 3);
        float bb0 = b1[col], bb1 = b1[col + 1];
#pragma unroll
        for (int half = 0; half < 2; half++) {
            int r = wm * 16 + (lane >> 2) + half * 8;
            int node = node0 + r;
            if (node < NN) {
                float inv = 1.0f / (dens[r * 4 + wn] + 1e-16f);
                float v0 = fmaxf(acc[nt][half * 2 + 0] * inv + bb0, 0.f);
                float v1 = fmaxf(acc[nt][half * 2 + 1] * inv + bb1, 0.f);
                *(float2*)&g_out1[(size_t)node * 256 + col] = make_float2(v0, v1);
            }
        }
    }
}

// ============ K4: g2 = out1 @ W2 (tf32) + fused alpha2 logits ============
__global__ void __launch_bounds__(256) gemm2_alpha2(const float* __restrict__ W2,
                                                    const float* __restrict__ a2s,
                                                    const float* __restrict__ a2d) {
    __shared__ float As[128][36];
    __shared__ float Bs2[32][72];
    __shared__ float sred[128][2];
    int tid = threadIdx.x, lane = tid & 31, wid = tid >> 5;
    int wm = wid >> 1, wn = wid & 1;
    int br = blockIdx.x * 128;
    if (tid < 128) { sred[tid][0] = 0.f; sred[tid][1] = 0.f; }

    float acc[2][4][4];
#pragma unroll
    for (int mt = 0; mt < 2; mt++)
#pragma unroll
        for (int nt = 0; nt < 4; nt++)
#pragma unroll
            for (int r = 0; r < 4; r++) acc[mt][nt][r] = 0.f;

    for (int k0 = 0; k0 < 256; k0 += 32) {
#pragma unroll
        for (int i = 0; i < 4; i++) {
            int id = tid + i * 256;
            int row = id >> 3, kq = id & 7;
            int gr = br + row;
            float4 v = make_float4(0,0,0,0);
            if (gr < NN) v = *(const float4*)&g_out1[(size_t)gr * 256 + k0 + kq * 4];
            As[row][kq * 4 + 0] = __uint_as_float(f2tf32(v.x));
            As[row][kq * 4 + 1] = __uint_as_float(f2tf32(v.y));
            As[row][kq * 4 + 2] = __uint_as_float(f2tf32(v.z));
            As[row][kq * 4 + 3] = __uint_as_float(f2tf32(v.w));
        }
#pragma unroll
        for (int i = 0; i < 2; i++) {
            int id = tid + i * 256;
            int kr = id >> 4, cq = id & 15;
            float4 v = *(const float4*)&W2[(size_t)(k0 + kr) * 64 + cq * 4];
            Bs2[kr][cq * 4 + 0] = __uint_as_float(f2tf32(v.x));
            Bs2[kr][cq * 4 + 1] = __uint_as_float(f2tf32(v.y));
            Bs2[kr][cq * 4 + 2] = __uint_as_float(f2tf32(v.z));
            Bs2[kr][cq * 4 + 3] = __uint_as_float(f2tf32(v.w));
        }
        __syncthreads();
#pragma unroll
        for (int kk = 0; kk < 32; kk += 8) {
            unsigned af[2][4];
#pragma unroll
            for (int mt = 0; mt < 2; mt++) {
                int rb = wm * 32 + mt * 16 + (lane >> 2);
                af[mt][0] = __float_as_uint(As[rb][kk + (lane & 3)]);
                af[mt][1] = __float_as_uint(As[rb + 8][kk + (lane & 3)]);
                af[mt][2] = __float_as_uint(As[rb][kk + 4 + (lane & 3)]);
                af[mt][3] = __float_as_uint(As[rb + 8][kk + 4 + (lane & 3)]);
            }
            unsigned bf[4][2];
#pragma unroll
            for (int nt = 0; nt < 4; nt++) {
                int cb = wn * 32 + nt * 8 + (lane >> 2);
                bf[nt][0] = __float_as_uint(Bs2[kk + (lane & 3)][cb]);
                bf[nt][1] = __float_as_uint(Bs2[kk + 4 + (lane & 3)][cb]);
            }
#pragma unroll
            for (int mt = 0; mt < 2; mt++)
#pragma unroll
                for (int nt = 0; nt < 4; nt++)
                    mma_tf32(acc[mt][nt][0], acc[mt][nt][1], acc[mt][nt][2], acc[mt][nt][3],
                             af[mt][0], af[mt][1], af[mt][2], af[mt][3],
                             bf[nt][0], bf[nt][1]);
        }
        __syncthreads();
    }

    // epilogue: write g2 + reduce alpha2 partials
#pragma unroll
    for (int mt = 0; mt < 2; mt++) {
#pragma unroll
        for (int half = 0; half < 2; half++) {
            int rl = wm * 32 + mt * 16 + (lane >> 2) + half * 8;
            int row = br + rl;
            float ss = 0.f, sd = 0.f;
            if (row < NN) {
#pragma unroll
                for (int nt = 0; nt < 4; nt++) {
                    int col = wn * 32 + nt * 8 + 2 * (lane & 3);
                    float v0 = acc[mt][nt][half * 2 + 0];
                    float v1 = acc[mt][nt][half * 2 + 1];
                    *(float2*)&g_g2[(size_t)row * 64 + col] = make_float2(v0, v1);
                    ss += v0 * a2s[col] + v1 * a2s[col + 1];
                    sd += v0 * a2d[col] + v1 * a2d[col + 1];
                }
                atomicAdd(&sred[rl][0], ss);
                atomicAdd(&sred[rl][1], sd);
            }
        }
    }
    __syncthreads();
    if (tid < 128) {
        int row = br + tid;
        if (row < NN) {
            g_asrc2[row] = sred[tid][0];
            g_adst2[row] = sred[tid][1];
        }
    }
}

// ============ K5: layer2 gather-aggregate + norm/bias/relu + FC ============
__global__ void __launch_bounds__(256) aggr2_fc(const float* __restrict__ b2,
                                                const float* __restrict__ Wfc,
                                                const float* __restrict__ bfc,
                                                float* __restrict__ out) {
    __shared__ float wf[64 * ACT];
    for (int i = threadIdx.x; i < 64 * ACT; i += blockDim.x)  // FIX: 320 entries, 256 threads
        wf[i] = Wfc[i];
    __syncthreads();
    int node = blockIdx.x * 8 + (threadIdx.x >> 5);
    int lane = threadIdx.x & 31;
    if (node >= NN) return;
    float ad = g_adst2[node];
    int s0 = g_off[node], s1 = g_off[node + 1];
    float2 acc = make_float2(0.f, 0.f);
    float den = 0.f;
    int i = s0;
    for (; i + 1 < s1; i += 2) {
        int sa = g_csr[i], sb = g_csr[i + 1];
        float pa = __expf(lrelu(g_asrc2[sa] + ad));
        float pb = __expf(lrelu(g_asrc2[sb] + ad));
        float2 va = *(const float2*)&g_g2[(size_t)sa * 64 + lane * 2];
        float2 vb = *(const float2*)&g_g2[(size_t)sb * 64 + lane * 2];
        acc.x += pa * va.x + pb * vb.x;
        acc.y += pa * va.y + pb * vb.y;
        den += pa + pb;
    }
    if (i < s1) {
        int sa = g_csr[i];
        float pa = __expf(lrelu(g_asrc2[sa] + ad));
        float2 va = *(const float2*)&g_g2[(size_t)sa * 64 + lane * 2];
        acc.x += pa * va.x;
        acc.y += pa * va.y;
        den += pa;
    }
    float inv = 1.0f / (den + 1e-16f);
    float2 bb = *(const float2*)&b2[lane * 2];
    float ox = fmaxf(acc.x * inv + bb.x, 0.f);
    float oy = fmaxf(acc.y * inv + bb.y, 0.f);
    float fa[ACT];
#pragma unroll
    for (int a = 0; a < ACT; a++)
        fa[a] = ox * wf[(2 * lane) * ACT + a] + oy * wf[(2 * lane + 1) * ACT + a];
#pragma unroll
    for (int a = 0; a < ACT; a++) {
#pragma unroll
        for (int o = 16; o > 0; o >>= 1)
            fa[a] += __shfl_down_sync(~0u, fa[a], o);
    }
    if (lane == 0) {
#pragma unroll
        for (int a = 0; a < ACT; a++)
            out[node * ACT + a] = fa[a] + bfc[a];
    }
}

// ---------------- launch ----------------
extern "C" void kernel_launch(void* const* d_in, const int* in_sizes, int n_in,
                              void* d_out, int out_size) {
    const float* x      = (const float*)d_in[0];
    const int*   ei     = (const int*)  d_in[1];
    const float* W1     = (const float*)d_in[2];
    const float* a1_src = (const float*)d_in[3];
    const float* a1_dst = (const float*)d_in[4];
    const float* b1     = (const float*)d_in[5];
    const float* W2     = (const float*)d_in[6];
    const float* a2_src = (const float*)d_in[7];
    const float* a2_dst = (const float*)d_in[8];
    const float* b2     = (const float*)d_in[9];
    const float* Wfc    = (const float*)d_in[10];
    const float* bfc    = (const float*)d_in[11];
    float* out = (float*)d_out;

    int E = in_sizes[1] / 2;
    int histB = (E + 255) / 256;

    cudaFuncSetAttribute(layer1_fused, cudaFuncAttributeMaxDynamicSharedMemorySize, L1_SMEM);

    // 0: histogram + w1a precompute
    hist_wpre<<<histB + 4, 256>>>(ei, E, histB, W1, a1_src, a1_dst);
    // 1: scan (block 0) + alpha1 logits (blocks 1..)
    scan_alpha<<<1 + (NN + 31) / 32, 1024>>>(x);
    // 2: scatter + per-slot softmax weights
    scatter_p<<<(E + NN + 255) / 256, 256>>>(ei, E);
    // 3: fused gather-aggregate + GEMM1 + epilogue   (<- profiled launch)
    layer1_fused<<<(NN + 31) / 32, 256, L1_SMEM>>>(x, W1, b1);
    // 4: GEMM2 + alpha2 logits
    gemm2_alpha2<<<(NN + 127) / 128, 256>>>(W2, a2_src, a2_dst);
    // 5: layer2 aggregate + FC
    aggr2_fc<<<(NN + 7) / 8, 256>>>(b2, Wfc, bfc, out);
}

// round 6
// speedup vs baseline: 1.9029x; 1.1142x over previous
#include <cuda_runtime.h>
#include <cuda_bf16.h>
#include <math.h>

#define NN    50000
#define EE    800000
#define INCH  128
#define HID   64
#define HEADS 4
#define ACT   5

// ---------------- scratch ----------------
__device__ float g_out1[NN * 256];
__device__ float g_asrc1[NN * 4];
__device__ float g_adst1[NN * 4];
__device__ float g_g2[NN * 64];
__device__ float g_asrc2[NN];
__device__ float g_adst2[NN];
__device__ float g_w1a[128 * 8];
__device__ int   g_cnt[NN];
__device__ int   g_off[NN + 1];
__device__ int   g_pos[NN];
__device__ int   g_csr[EE + NN];
__device__ float g_p[(EE + NN) * 4];

__device__ __forceinline__ float lrelu(float x) { return x > 0.0f ? x : 0.2f * x; }

__device__ __forceinline__ unsigned f2tf32(float f) {
    unsigned u;
    asm("cvt.rna.tf32.f32 %0, %1;" : "=r"(u) : "f"(f));
    return u;
}

__device__ __forceinline__ void mma_tf32(float& d0, float& d1, float& d2, float& d3,
                                         unsigned a0, unsigned a1, unsigned a2, unsigned a3,
                                         unsigned b0, unsigned b1) {
    asm volatile("mma.sync.aligned.m16n8k8.row.col.f32.tf32.tf32.f32 "
                 "{%0,%1,%2,%3},{%4,%5,%6,%7},{%8,%9},{%0,%1,%2,%3};"
                 : "+f"(d0), "+f"(d1), "+f"(d2), "+f"(d3)
                 : "r"(a0), "r"(a1), "r"(a2), "r"(a3), "r"(b0), "r"(b1));
}

// ============ K0: histogram + w1a precompute ============
__global__ void hist_wpre(const int* __restrict__ ei, int E, int histB,
                          const float* __restrict__ W1,
                          const float* __restrict__ a1s,
                          const float* __restrict__ a1d) {
    if ((int)blockIdx.x < histB) {
        int e = blockIdx.x * 256 + threadIdx.x;
        if (e < E) atomicAdd(&g_cnt[ei[E + e]], 1);
    } else {
        int t = (blockIdx.x - histB) * 256 + threadIdx.x;
        if (t < 1024) {
            int k = t >> 3, j = t & 7, h = j & 3;
            const float* av = (j < 4 ? a1s : a1d) + h * 64;
            const float* wr = W1 + (size_t)k * 256 + h * 64;
            float s = 0.f;
#pragma unroll 8
            for (int c = 0; c < 64; c++) s += wr[c] * av[c];
            g_w1a[k * 8 + j] = s;
        }
    }
}

// ============ K1: scan (block 0) + alpha1 (blocks 1..) ============
__global__ void __launch_bounds__(1024) scan_alpha(const float* __restrict__ x) {
    __shared__ float w1s[128 * 8];
    if (blockIdx.x == 0) {
        __shared__ int ws[32];
        const int T = 1024;
        const int CH = (NN + T - 1) / T;
        int tid = threadIdx.x;
        int base = tid * CH;
        int cnts[49];
        int local = 0;
        for (int j = 0; j < CH; j++) {
            int idx = base + j;
            int c = 0;
            if (idx < NN) { c = g_cnt[idx] + 1; g_cnt[idx] = 0; }
            cnts[j] = c;
            local += c;
        }
        int lane = tid & 31, wid = tid >> 5;
        int v = local;
#pragma unroll
        for (int o = 1; o < 32; o <<= 1) { int y = __shfl_up_sync(~0u, v, o); if (lane >= o) v += y; }
        if (lane == 31) ws[wid] = v;
        __syncthreads();
        if (wid == 0) {
            int w = ws[lane];
#pragma unroll
            for (int o = 1; o < 32; o <<= 1) { int y = __shfl_up_sync(~0u, w, o); if (lane >= o) w += y; }
            ws[lane] = w;
        }
        __syncthreads();
        int run = v - local + (wid > 0 ? ws[wid - 1] : 0);
        for (int j = 0; j < CH; j++) {
            int idx = base + j;
            if (idx < NN) {
                g_off[idx] = run;
                g_pos[idx] = run;
                run += cnts[j];
            }
        }
        if (tid == T - 1) g_off[NN] = run;
    } else {
        int tid = threadIdx.x;
        if (tid < 1024) w1s[tid] = g_w1a[tid];
        __syncthreads();
        int wid = tid >> 5, lane = tid & 31;
        int node = (blockIdx.x - 1) * 32 + wid;
        if (node >= NN) return;
        float4 xv = *(const float4*)&x[(size_t)node * 128 + lane * 4];
        float s[8];
#pragma unroll
        for (int j = 0; j < 8; j++) s[j] = 0.f;
#pragma unroll
        for (int k = 0; k < 4; k++) {
            float xk = (&xv.x)[k];
            const float* wr = &w1s[(lane * 4 + k) * 8];
            float4 wa = *(const float4*)&wr[0];
            float4 wb = *(const float4*)&wr[4];
            s[0] += xk * wa.x; s[1] += xk * wa.y; s[2] += xk * wa.z; s[3] += xk * wa.w;
            s[4] += xk * wb.x; s[5] += xk * wb.y; s[6] += xk * wb.z; s[7] += xk * wb.w;
        }
#pragma unroll
        for (int j = 0; j < 8; j++) {
#pragma unroll
            for (int o = 16; o > 0; o >>= 1) s[j] += __shfl_xor_sync(~0u, s[j], o);
        }
        if (lane == 0) {
            *(float4*)&g_asrc1[node * 4] = make_float4(s[0], s[1], s[2], s[3]);
            *(float4*)&g_adst1[node * 4] = make_float4(s[4], s[5], s[6], s[7]);
        }
    }
}

// ============ K2: scatter + per-slot softmax weights ============
__global__ void scatter_p(const int* __restrict__ ei, int E) {
    int t = blockIdx.x * blockDim.x + threadIdx.x;
    int src, dst;
    if (t < E) { src = ei[t]; dst = ei[E + t]; }
    else if (t < E + NN) { src = dst = t - E; }
    else return;
    int pos = atomicAdd(&g_pos[dst], 1);
    g_csr[pos] = src;
    float4 es = *(const float4*)&g_asrc1[src * 4];
    float4 ed = *(const float4*)&g_adst1[dst * 4];
    float4 p;
    p.x = __expf(lrelu(es.x + ed.x));
    p.y = __expf(lrelu(es.y + ed.y));
    p.z = __expf(lrelu(es.z + ed.z));
    p.w = __expf(lrelu(es.w + ed.w));
    *(float4*)&g_p[(size_t)pos * 4] = p;
}

// ============ K3: fused gather-aggregate + tf32 GEMM1 + norm/bias/relu ============
// 512 threads (16 warps), 32 nodes/block. smem: As[128][132], Bs[32][260], dens[128]
#define L1_SMEM ((128 * 132 + 32 * 260 + 128) * 4)
__global__ void __launch_bounds__(512, 2) layer1_fused(const float* __restrict__ x,
                                                       const float* __restrict__ W1,
                                                       const float* __restrict__ b1) {
    extern __shared__ float sm[];
    float* As = sm;                       // 128 rows (head*32+node) x 132
    float* Bs = sm + 128 * 132;           // 32 k x 260 (256 cols + pad)
    float* dens = Bs + 32 * 260;          // 128 (node*4+head)
    int tid = threadIdx.x, lane = tid & 31, wid = tid >> 5;
    int node0 = blockIdx.x * 32;

    // ---- phase 1: gather (16 warps, 2 nodes each) ----
    for (int nl = wid; nl < 32; nl += 16) {
        int node = node0 + nl;
        float4 a0 = make_float4(0,0,0,0), a1 = a0, a2 = a0, a3 = a0;
        float4 dn = a0;
        if (node < NN) {
            int s0 = g_off[node], s1 = g_off[node + 1];
            int i = s0;
            for (; i + 1 < s1; i += 2) {
                int sa = g_csr[i], sb = g_csr[i + 1];
                float4 pa = *(const float4*)&g_p[(size_t)i * 4];
                float4 pb = *(const float4*)&g_p[(size_t)(i + 1) * 4];
                float4 xa = *(const float4*)&x[(size_t)sa * 128 + lane * 4];
                float4 xb = *(const float4*)&x[(size_t)sb * 128 + lane * 4];
                a0.x += pa.x * xa.x + pb.x * xb.x; a0.y += pa.x * xa.y + pb.x * xb.y;
                a0.z += pa.x * xa.z + pb.x * xb.z; a0.w += pa.x * xa.w + pb.x * xb.w;
                a1.x += pa.y * xa.x + pb.y * xb.x; a1.y += pa.y * xa.y + pb.y * xb.y;
                a1.z += pa.y * xa.z + pb.y * xb.z; a1.w += pa.y * xa.w + pb.y * xb.w;
                a2.x += pa.z * xa.x + pb.z * xb.x; a2.y += pa.z * xa.y + pb.z * xb.y;
                a2.z += pa.z * xa.z + pb.z * xb.z; a2.w += pa.z * xa.w + pb.z * xb.w;
                a3.x += pa.w * xa.x + pb.w * xb.x; a3.y += pa.w * xa.y + pb.w * xb.y;
                a3.z += pa.w * xa.z + pb.w * xb.z; a3.w += pa.w * xa.w + pb.w * xb.w;
                dn.x += pa.x + pb.x; dn.y += pa.y + pb.y;
                dn.z += pa.z + pb.z; dn.w += pa.w + pb.w;
            }
            if (i < s1) {
                int sa = g_csr[i];
                float4 pa = *(const float4*)&g_p[(size_t)i * 4];
                float4 xa = *(const float4*)&x[(size_t)sa * 128 + lane * 4];
                a0.x += pa.x * xa.x; a0.y += pa.x * xa.y; a0.z += pa.x * xa.z; a0.w += pa.x * xa.w;
                a1.x += pa.y * xa.x; a1.y += pa.y * xa.y; a1.z += pa.y * xa.z; a1.w += pa.y * xa.w;
                a2.x += pa.z * xa.x; a2.y += pa.z * xa.y; a2.z += pa.z * xa.z; a2.w += pa.z * xa.w;
                a3.x += pa.w * xa.x; a3.y += pa.w * xa.y; a3.z += pa.w * xa.z; a3.w += pa.w * xa.w;
                dn.x += pa.x; dn.y += pa.y; dn.z += pa.z; dn.w += pa.w;
            }
        }
        float4 c0, c1, c2, c3;
        c0.x = __uint_as_float(f2tf32(a0.x)); c0.y = __uint_as_float(f2tf32(a0.y));
        c0.z = __uint_as_float(f2tf32(a0.z)); c0.w = __uint_as_float(f2tf32(a0.w));
        c1.x = __uint_as_float(f2tf32(a1.x)); c1.y = __uint_as_float(f2tf32(a1.y));
        c1.z = __uint_as_float(f2tf32(a1.z)); c1.w = __uint_as_float(f2tf32(a1.w));
        c2.x = __uint_as_float(f2tf32(a2.x)); c2.y = __uint_as_float(f2tf32(a2.y));
        c2.z = __uint_as_float(f2tf32(a2.z)); c2.w = __uint_as_float(f2tf32(a2.w));
        c3.x = __uint_as_float(f2tf32(a3.x)); c3.y = __uint_as_float(f2tf32(a3.y));
        c3.z = __uint_as_float(f2tf32(a3.z)); c3.w = __uint_as_float(f2tf32(a3.w));
        *(float4*)&As[(0 * 32 + nl) * 132 + lane * 4] = c0;
        *(float4*)&As[(1 * 32 + nl) * 132 + lane * 4] = c1;
        *(float4*)&As[(2 * 32 + nl) * 132 + lane * 4] = c2;
        *(float4*)&As[(3 * 32 + nl) * 132 + lane * 4] = c3;
        if (lane == 0) {
            dens[nl * 4 + 0] = dn.x; dens[nl * 4 + 1] = dn.y;
            dens[nl * 4 + 2] = dn.z; dens[nl * 4 + 3] = dn.w;
        }
    }
    __syncthreads();

    // ---- phase 2: per-head GEMM, 16 warps: wn = head, wm = (rowHalf | colHalf<<1) ----
    int wn = wid & 3;          // head
    int wm = wid >> 2;         // 0..3
    int rowHalf = wm & 1;      // 16-row half within the head's 32 nodes
    int colHalf = wm >> 1;     // 32-col half within the head's 64 cols
    float acc[4][4];
#pragma unroll
    for (int nt = 0; nt < 4; nt++)
#pragma unroll
        for (int r = 0; r < 4; r++) acc[nt][r] = 0.f;

    for (int kc = 0; kc < 4; kc++) {
#pragma unroll
        for (int i = 0; i < 4; i++) {
            int id = tid + i * 512;          // 0..2047
            int kr = id >> 6, cq = id & 63;
            float4 v = *(const float4*)&W1[(size_t)(kc * 32 + kr) * 256 + cq * 4];
            Bs[kr * 260 + cq * 4 + 0] = __uint_as_float(f2tf32(v.x));
            Bs[kr * 260 + cq * 4 + 1] = __uint_as_float(f2tf32(v.y));
            Bs[kr * 260 + cq * 4 + 2] = __uint_as_float(f2tf32(v.z));
            Bs[kr * 260 + cq * 4 + 3] = __uint_as_float(f2tf32(v.w));
        }
        __syncthreads();
#pragma unroll
        for (int kk = 0; kk < 32; kk += 8) {
            int k0 = kc * 32 + kk;
            int ar = wn * 32 + rowHalf * 16 + (lane >> 2);
            unsigned a0 = __float_as_uint(As[ar * 132 + k0 + (lane & 3)]);
            unsigned a1 = __float_as_uint(As[(ar + 8) * 132 + k0 + (lane & 3)]);
            unsigned a2 = __float_as_uint(As[ar * 132 + k0 + 4 + (lane & 3)]);
            unsigned a3 = __float_as_uint(As[(ar + 8) * 132 + k0 + 4 + (lane & 3)]);
#pragma unroll
            for (int nt = 0; nt < 4; nt++) {
                int cb = wn * 64 + colHalf * 32 + nt * 8 + (lane >> 2);
                unsigned b0 = __float_as_uint(Bs[(kk + (lane & 3)) * 260 + cb]);
                unsigned b1v = __float_as_uint(Bs[(kk + 4 + (lane & 3)) * 260 + cb]);
                mma_tf32(acc[nt][0], acc[nt][1], acc[nt][2], acc[nt][3],
                         a0, a1, a2, a3, b0, b1v);
            }
        }
        __syncthreads();
    }

    // ---- epilogue ----
#pragma unroll
    for (int nt = 0; nt < 4; nt++) {
        int col = wn * 64 + colHalf * 32 + nt * 8 + 2 * (lane & 3);
        float bb0 = b1[col], bb1 = b1[col + 1];
#pragma unroll
        for (int half = 0; half < 2; half++) {
            int r = rowHalf * 16 + (lane >> 2) + half * 8;
            int node = node0 + r;
            if (node < NN) {
                float inv = 1.0f / (dens[r * 4 + wn] + 1e-16f);
                float v0 = fmaxf(acc[nt][half * 2 + 0] * inv + bb0, 0.f);
                float v1 = fmaxf(acc[nt][half * 2 + 1] * inv + bb1, 0.f);
                *(float2*)&g_out1[(size_t)node * 256 + col] = make_float2(v0, v1);
            }
        }
    }
}

// ============ K4: g2 = out1 @ W2 (tf32) + fused alpha2 logits ============
__global__ void __launch_bounds__(256) gemm2_alpha2(const float* __restrict__ W2,
                                                    const float* __restrict__ a2s,
                                                    const float* __restrict__ a2d) {
    __shared__ float As[128][36];
    __shared__ float Bs2[32][72];
    __shared__ float sred[128][2];
    int tid = threadIdx.x, lane = tid & 31, wid = tid >> 5;
    int wm = wid >> 1, wn = wid & 1;
    int br = blockIdx.x * 128;
    if (tid < 128) { sred[tid][0] = 0.f; sred[tid][1] = 0.f; }

    float acc[2][4][4];
#pragma unroll
    for (int mt = 0; mt < 2; mt++)
#pragma unroll
        for (int nt = 0; nt < 4; nt++)
#pragma unroll
            for (int r = 0; r < 4; r++) acc[mt][nt][r] = 0.f;

    for (int k0 = 0; k0 < 256; k0 += 32) {
#pragma unroll
        for (int i = 0; i < 4; i++) {
            int id = tid + i * 256;
            int row = id >> 3, kq = id & 7;
            int gr = br + row;
            float4 v = make_float4(0,0,0,0);
            if (gr < NN) v = *(const float4*)&g_out1[(size_t)gr * 256 + k0 + kq * 4];
            As[row][kq * 4 + 0] = __uint_as_float(f2tf32(v.x));
            As[row][kq * 4 + 1] = __uint_as_float(f2tf32(v.y));
            As[row][kq * 4 + 2] = __uint_as_float(f2tf32(v.z));
            As[row][kq * 4 + 3] = __uint_as_float(f2tf32(v.w));
        }
#pragma unroll
        for (int i = 0; i < 2; i++) {
            int id = tid + i * 256;
            int kr = id >> 4, cq = id & 15;
            float4 v = *(const float4*)&W2[(size_t)(k0 + kr) * 64 + cq * 4];
            Bs2[kr][cq * 4 + 0] = __uint_as_float(f2tf32(v.x));
            Bs2[kr][cq * 4 + 1] = __uint_as_float(f2tf32(v.y));
            Bs2[kr][cq * 4 + 2] = __uint_as_float(f2tf32(v.z));
            Bs2[kr][cq * 4 + 3] = __uint_as_float(f2tf32(v.w));
        }
        __syncthreads();
#pragma unroll
        for (int kk = 0; kk < 32; kk += 8) {
            unsigned af[2][4];
#pragma unroll
            for (int mt = 0; mt < 2; mt++) {
                int rb = wm * 32 + mt * 16 + (lane >> 2);
                af[mt][0] = __float_as_uint(As[rb][kk + (lane & 3)]);
                af[mt][1] = __float_as_uint(As[rb + 8][kk + (lane & 3)]);
                af[mt][2] = __float_as_uint(As[rb][kk + 4 + (lane & 3)]);
                af[mt][3] = __float_as_uint(As[rb + 8][kk + 4 + (lane & 3)]);
            }
            unsigned bf[4][2];
#pragma unroll
            for (int nt = 0; nt < 4; nt++) {
                int cb = wn * 32 + nt * 8 + (lane >> 2);
                bf[nt][0] = __float_as_uint(Bs2[kk + (lane & 3)][cb]);
                bf[nt][1] = __float_as_uint(Bs2[kk + 4 + (lane & 3)][cb]);
            }
#pragma unroll
            for (int mt = 0; mt < 2; mt++)
#pragma unroll
                for (int nt = 0; nt < 4; nt++)
                    mma_tf32(acc[mt][nt][0], acc[mt][nt][1], acc[mt][nt][2], acc[mt][nt][3],
                             af[mt][0], af[mt][1], af[mt][2], af[mt][3],
                             bf[nt][0], bf[nt][1]);
        }
        __syncthreads();
    }

#pragma unroll
    for (int mt = 0; mt < 2; mt++) {
#pragma unroll
        for (int half = 0; half < 2; half++) {
            int rl = wm * 32 + mt * 16 + (lane >> 2) + half * 8;
            int row = br + rl;
            float ss = 0.f, sd = 0.f;
            if (row < NN) {
#pragma unroll
                for (int nt = 0; nt < 4; nt++) {
                    int col = wn * 32 + nt * 8 + 2 * (lane & 3);
                    float v0 = acc[mt][nt][half * 2 + 0];
                    float v1 = acc[mt][nt][half * 2 + 1];
                    *(float2*)&g_g2[(size_t)row * 64 + col] = make_float2(v0, v1);
                    ss += v0 * a2s[col] + v1 * a2s[col + 1];
                    sd += v0 * a2d[col] + v1 * a2d[col + 1];
                }
                atomicAdd(&sred[rl][0], ss);
                atomicAdd(&sred[rl][1], sd);
            }
        }
    }
    __syncthreads();
    if (tid < 128) {
        int row = br + tid;
        if (row < NN) {
            g_asrc2[row] = sred[tid][0];
            g_adst2[row] = sred[tid][1];
        }
    }
}

// ============ K5: layer2 gather-aggregate + norm/bias/relu + FC ============
__global__ void __launch_bounds__(256) aggr2_fc(const float* __restrict__ b2,
                                                const float* __restrict__ Wfc,
                                                const float* __restrict__ bfc,
                                                float* __restrict__ out) {
    __shared__ float wf[64 * ACT];
    for (int i = threadIdx.x; i < 64 * ACT; i += blockDim.x)
        wf[i] = Wfc[i];
    __syncthreads();
    int node = blockIdx.x * 8 + (threadIdx.x >> 5);
    int lane = threadIdx.x & 31;
    if (node >= NN) return;
    float ad = g_adst2[node];
    int s0 = g_off[node], s1 = g_off[node + 1];
    float2 acc = make_float2(0.f, 0.f);
    float den = 0.f;
    int i = s0;
    for (; i + 3 < s1; i += 4) {
        int sa = g_csr[i], sb = g_csr[i + 1], sc = g_csr[i + 2], sd = g_csr[i + 3];
        float pa = __expf(lrelu(g_asrc2[sa] + ad));
        float pb = __expf(lrelu(g_asrc2[sb] + ad));
        float pc = __expf(lrelu(g_asrc2[sc] + ad));
        float pd = __expf(lrelu(g_asrc2[sd] + ad));
        float2 va = *(const float2*)&g_g2[(size_t)sa * 64 + lane * 2];
        float2 vb = *(const float2*)&g_g2[(size_t)sb * 64 + lane * 2];
        float2 vc = *(const float2*)&g_g2[(size_t)sc * 64 + lane * 2];
        float2 vd = *(const float2*)&g_g2[(size_t)sd * 64 + lane * 2];
        acc.x += pa * va.x + pb * vb.x + pc * vc.x + pd * vd.x;
        acc.y += pa * va.y + pb * vb.y + pc * vc.y + pd * vd.y;
        den += pa + pb + pc + pd;
    }
    for (; i < s1; i++) {
        int sa = g_csr[i];
        float pa = __expf(lrelu(g_asrc2[sa] + ad));
        float2 va = *(const float2*)&g_g2[(size_t)sa * 64 + lane * 2];
        acc.x += pa * va.x;
        acc.y += pa * va.y;
        den += pa;
    }
    float inv = 1.0f / (den + 1e-16f);
    float2 bb = *(const float2*)&b2[lane * 2];
    float ox = fmaxf(acc.x * inv + bb.x, 0.f);
    float oy = fmaxf(acc.y * inv + bb.y, 0.f);
    float fa[ACT];
#pragma unroll
    for (int a = 0; a < ACT; a++)
        fa[a] = ox * wf[(2 * lane) * ACT + a] + oy * wf[(2 * lane + 1) * ACT + a];
#pragma unroll
    for (int a = 0; a < ACT; a++) {
#pragma unroll
        for (int o = 16; o > 0; o >>= 1)
            fa[a] += __shfl_down_sync(~0u, fa[a], o);
    }
    if (lane == 0) {
#pragma unroll
        for (int a = 0; a < ACT; a++)
            out[node * ACT + a] = fa[a] + bfc[a];
    }
}

// ---------------- launch ----------------
extern "C" void kernel_launch(void* const* d_in, const int* in_sizes, int n_in,
                              void* d_out, int out_size) {
    const float* x      = (const float*)d_in[0];
    const int*   ei     = (const int*)  d_in[1];
    const float* W1     = (const float*)d_in[2];
    const float* a1_src = (const float*)d_in[3];
    const float* a1_dst = (const float*)d_in[4];
    const float* b1     = (const float*)d_in[5];
    const float* W2     = (const float*)d_in[6];
    const float* a2_src = (const float*)d_in[7];
    const float* a2_dst = (const float*)d_in[8];
    const float* b2     = (const float*)d_in[9];
    const float* Wfc    = (const float*)d_in[10];
    const float* bfc    = (const float*)d_in[11];
    float* out = (float*)d_out;

    int E = in_sizes[1] / 2;
    int histB = (E + 255) / 256;

    cudaFuncSetAttribute(layer1_fused, cudaFuncAttributeMaxDynamicSharedMemorySize, L1_SMEM);

    // 0: histogram + w1a precompute
    hist_wpre<<<histB + 4, 256>>>(ei, E, histB, W1, a1_src, a1_dst);
    // 1: scan + alpha1
    scan_alpha<<<1 + (NN + 31) / 32, 1024>>>(x);
    // 2: scatter + softmax weights
    scatter_p<<<(E + NN + 255) / 256, 256>>>(ei, E);
    // 3: fused gather + GEMM1 + epilogue   (<- profiled launch)
    layer1_fused<<<(NN + 31) / 32, 512, L1_SMEM>>>(x, W1, b1);
    // 4: GEMM2 + alpha2
    gemm2_alpha2<<<(NN + 127) / 128, 256>>>(W2, a2_src, a2_dst);
    // 5: layer2 aggregate + FC
    aggr2_fc<<<(NN + 7) / 8, 256>>>(b2, Wfc, bfc, out);
}

// round 7
// speedup vs baseline: 1.9372x; 1.0180x over previous
#include <cuda_runtime.h>
#include <cuda_bf16.h>
#include <math.h>

#define NN    50000
#define EE    800000
#define INCH  128
#define HID   64
#define HEADS 4
#define ACT   5

// ---------------- scratch ----------------
__device__ float g_out1[NN * 256];
__device__ float g_asrc1[NN * 4];
__device__ float g_adst1[NN * 4];
__device__ float g_g2[NN * 64];
__device__ float g_asrc2[NN];
__device__ float g_adst2[NN];
__device__ float g_w1a[128 * 8];
__device__ int   g_cnt[NN];
__device__ int   g_off[NN + 1];
__device__ int   g_pos[NN];
__device__ int   g_csr[EE + NN];
__device__ float g_p[(EE + NN) * 4];

__device__ __forceinline__ float lrelu(float x) { return x > 0.0f ? x : 0.2f * x; }

__device__ __forceinline__ unsigned f2tf32(float f) {
    unsigned u;
    asm("cvt.rna.tf32.f32 %0, %1;" : "=r"(u) : "f"(f));
    return u;
}

__device__ __forceinline__ void mma_tf32(float& d0, float& d1, float& d2, float& d3,
                                         unsigned a0, unsigned a1, unsigned a2, unsigned a3,
                                         unsigned b0, unsigned b1) {
    asm volatile("mma.sync.aligned.m16n8k8.row.col.f32.tf32.tf32.f32 "
                 "{%0,%1,%2,%3},{%4,%5,%6,%7},{%8,%9},{%0,%1,%2,%3};"
                 : "+f"(d0), "+f"(d1), "+f"(d2), "+f"(d3)
                 : "r"(a0), "r"(a1), "r"(a2), "r"(a3), "r"(b0), "r"(b1));
}

// ============ K0: histogram + w1a precompute ============
__global__ void hist_wpre(const int* __restrict__ ei, int E, int histB,
                          const float* __restrict__ W1,
                          const float* __restrict__ a1s,
                          const float* __restrict__ a1d) {
    if ((int)blockIdx.x < histB) {
        int e = blockIdx.x * 256 + threadIdx.x;
        if (e < E) atomicAdd(&g_cnt[ei[E + e]], 1);
    } else {
        int t = (blockIdx.x - histB) * 256 + threadIdx.x;
        if (t < 1024) {
            int k = t >> 3, j = t & 7, h = j & 3;
            const float* av = (j < 4 ? a1s : a1d) + h * 64;
            const float* wr = W1 + (size_t)k * 256 + h * 64;
            float s = 0.f;
#pragma unroll 8
            for (int c = 0; c < 64; c++) s += wr[c] * av[c];
            g_w1a[k * 8 + j] = s;
        }
    }
}

// ============ K1: scan (block 0) + alpha1 (blocks 1..) ============
__global__ void __launch_bounds__(1024) scan_alpha(const float* __restrict__ x) {
    __shared__ float w1s[128 * 8];
    if (blockIdx.x == 0) {
        __shared__ int ws[32];
        const int T = 1024;
        const int CH = (NN + T - 1) / T;
        int tid = threadIdx.x;
        int base = tid * CH;
        int cnts[49];
        int local = 0;
        for (int j = 0; j < CH; j++) {
            int idx = base + j;
            int c = 0;
            if (idx < NN) { c = g_cnt[idx] + 1; g_cnt[idx] = 0; }
            cnts[j] = c;
            local += c;
        }
        int lane = tid & 31, wid = tid >> 5;
        int v = local;
#pragma unroll
        for (int o = 1; o < 32; o <<= 1) { int y = __shfl_up_sync(~0u, v, o); if (lane >= o) v += y; }
        if (lane == 31) ws[wid] = v;
        __syncthreads();
        if (wid == 0) {
            int w = ws[lane];
#pragma unroll
            for (int o = 1; o < 32; o <<= 1) { int y = __shfl_up_sync(~0u, w, o); if (lane >= o) w += y; }
            ws[lane] = w;
        }
        __syncthreads();
        int run = v - local + (wid > 0 ? ws[wid - 1] : 0);
        for (int j = 0; j < CH; j++) {
            int idx = base + j;
            if (idx < NN) {
                g_off[idx] = run;
                g_pos[idx] = run;
                run += cnts[j];
            }
        }
        if (tid == T - 1) g_off[NN] = run;
    } else {
        int tid = threadIdx.x;
        if (tid < 1024) w1s[tid] = g_w1a[tid];
        __syncthreads();
        int wid = tid >> 5, lane = tid & 31;
        int node = (blockIdx.x - 1) * 32 + wid;
        if (node >= NN) return;
        float4 xv = *(const float4*)&x[(size_t)node * 128 + lane * 4];
        float s[8];
#pragma unroll
        for (int j = 0; j < 8; j++) s[j] = 0.f;
#pragma unroll
        for (int k = 0; k < 4; k++) {
            float xk = (&xv.x)[k];
            const float* wr = &w1s[(lane * 4 + k) * 8];
            float4 wa = *(const float4*)&wr[0];
            float4 wb = *(const float4*)&wr[4];
            s[0] += xk * wa.x; s[1] += xk * wa.y; s[2] += xk * wa.z; s[3] += xk * wa.w;
            s[4] += xk * wb.x; s[5] += xk * wb.y; s[6] += xk * wb.z; s[7] += xk * wb.w;
        }
#pragma unroll
        for (int j = 0; j < 8; j++) {
#pragma unroll
            for (int o = 16; o > 0; o >>= 1) s[j] += __shfl_xor_sync(~0u, s[j], o);
        }
        if (lane == 0) {
            *(float4*)&g_asrc1[node * 4] = make_float4(s[0], s[1], s[2], s[3]);
            *(float4*)&g_adst1[node * 4] = make_float4(s[4], s[5], s[6], s[7]);
        }
    }
}

// ============ K2: scatter + per-slot softmax weights ============
__global__ void scatter_p(const int* __restrict__ ei, int E) {
    int t = blockIdx.x * blockDim.x + threadIdx.x;
    int src, dst;
    if (t < E) { src = ei[t]; dst = ei[E + t]; }
    else if (t < E + NN) { src = dst = t - E; }
    else return;
    int pos = atomicAdd(&g_pos[dst], 1);
    g_csr[pos] = src;
    float4 es = *(const float4*)&g_asrc1[src * 4];
    float4 ed = *(const float4*)&g_adst1[dst * 4];
    float4 p;
    p.x = __expf(lrelu(es.x + ed.x));
    p.y = __expf(lrelu(es.y + ed.y));
    p.z = __expf(lrelu(es.z + ed.z));
    p.w = __expf(lrelu(es.w + ed.w));
    *(float4*)&g_p[(size_t)pos * 4] = p;
}

// ============ K3: fused gather-aggregate + tf32 GEMM1 + norm/bias/relu ============
// 512 threads (16 warps), 32 nodes/block. Gather software-pipelined unroll-4.
#define L1_SMEM ((128 * 132 + 32 * 260 + 128) * 4)
__global__ void __launch_bounds__(512, 2) layer1_fused(const float* __restrict__ x,
                                                       const float* __restrict__ W1,
                                                       const float* __restrict__ b1) {
    extern __shared__ float sm[];
    float* As = sm;                       // 128 rows (head*32+node) x 132
    float* Bs = sm + 128 * 132;           // 32 k x 260
    float* dens = Bs + 32 * 260;          // 128
    int tid = threadIdx.x, lane = tid & 31, wid = tid >> 5;
    int node0 = blockIdx.x * 32;

    // ---- phase 1: gather (16 warps, 2 nodes each), unroll-4 pipelined ----
    for (int nl = wid; nl < 32; nl += 16) {
        int node = node0 + nl;
        float4 a0 = make_float4(0,0,0,0), a1 = a0, a2 = a0, a3 = a0;
        float4 dn = a0;
        if (node < NN) {
            int s0 = g_off[node], s1 = g_off[node + 1];
            int i = s0;
            for (; i + 3 < s1; i += 4) {
                // independent index/weight loads (L2/L1 resident, uniform)
                int e0 = g_csr[i],     e1 = g_csr[i + 1];
                int e2 = g_csr[i + 2], e3 = g_csr[i + 3];
                float4 p0 = *(const float4*)&g_p[(size_t)(i)     * 4];
                float4 p1 = *(const float4*)&g_p[(size_t)(i + 1) * 4];
                float4 p2 = *(const float4*)&g_p[(size_t)(i + 2) * 4];
                float4 p3 = *(const float4*)&g_p[(size_t)(i + 3) * 4];
                // 4 independent x-row loads -> MLP 4
                float4 x0 = *(const float4*)&x[(size_t)e0 * 128 + lane * 4];
                float4 x1 = *(const float4*)&x[(size_t)e1 * 128 + lane * 4];
                float4 x2 = *(const float4*)&x[(size_t)e2 * 128 + lane * 4];
                float4 x3 = *(const float4*)&x[(size_t)e3 * 128 + lane * 4];
                a0.x += p0.x*x0.x + p1.x*x1.x + p2.x*x2.x + p3.x*x3.x;
                a0.y += p0.x*x0.y + p1.x*x1.y + p2.x*x2.y + p3.x*x3.y;
                a0.z += p0.x*x0.z + p1.x*x1.z + p2.x*x2.z + p3.x*x3.z;
                a0.w += p0.x*x0.w + p1.x*x1.w + p2.x*x2.w + p3.x*x3.w;
                a1.x += p0.y*x0.x + p1.y*x1.x + p2.y*x2.x + p3.y*x3.x;
                a1.y += p0.y*x0.y + p1.y*x1.y + p2.y*x2.y + p3.y*x3.y;
                a1.z += p0.y*x0.z + p1.y*x1.z + p2.y*x2.z + p3.y*x3.z;
                a1.w += p0.y*x0.w + p1.y*x1.w + p2.y*x2.w + p3.y*x3.w;
                a2.x += p0.z*x0.x + p1.z*x1.x + p2.z*x2.x + p3.z*x3.x;
                a2.y += p0.z*x0.y + p1.z*x1.y + p2.z*x2.y + p3.z*x3.y;
                a2.z += p0.z*x0.z + p1.z*x1.z + p2.z*x2.z + p3.z*x3.z;
                a2.w += p0.z*x0.w + p1.z*x1.w + p2.z*x2.w + p3.z*x3.w;
                a3.x += p0.w*x0.x + p1.w*x1.x + p2.w*x2.x + p3.w*x3.x;
                a3.y += p0.w*x0.y + p1.w*x1.y + p2.w*x2.y + p3.w*x3.y;
                a3.z += p0.w*x0.z + p1.w*x1.z + p2.w*x2.z + p3.w*x3.z;
                a3.w += p0.w*x0.w + p1.w*x1.w + p2.w*x2.w + p3.w*x3.w;
                dn.x += p0.x + p1.x + p2.x + p3.x;
                dn.y += p0.y + p1.y + p2.y + p3.y;
                dn.z += p0.z + p1.z + p2.z + p3.z;
                dn.w += p0.w + p1.w + p2.w + p3.w;
            }
            for (; i < s1; i++) {
                int sa = g_csr[i];
                float4 pa = *(const float4*)&g_p[(size_t)i * 4];
                float4 xa = *(const float4*)&x[(size_t)sa * 128 + lane * 4];
                a0.x += pa.x * xa.x; a0.y += pa.x * xa.y; a0.z += pa.x * xa.z; a0.w += pa.x * xa.w;
                a1.x += pa.y * xa.x; a1.y += pa.y * xa.y; a1.z += pa.y * xa.z; a1.w += pa.y * xa.w;
                a2.x += pa.z * xa.x; a2.y += pa.z * xa.y; a2.z += pa.z * xa.z; a2.w += pa.z * xa.w;
                a3.x += pa.w * xa.x; a3.y += pa.w * xa.y; a3.z += pa.w * xa.z; a3.w += pa.w * xa.w;
                dn.x += pa.x; dn.y += pa.y; dn.z += pa.z; dn.w += pa.w;
            }
        }
        float4 c0, c1, c2, c3;
        c0.x = __uint_as_float(f2tf32(a0.x)); c0.y = __uint_as_float(f2tf32(a0.y));
        c0.z = __uint_as_float(f2tf32(a0.z)); c0.w = __uint_as_float(f2tf32(a0.w));
        c1.x = __uint_as_float(f2tf32(a1.x)); c1.y = __uint_as_float(f2tf32(a1.y));
        c1.z = __uint_as_float(f2tf32(a1.z)); c1.w = __uint_as_float(f2tf32(a1.w));
        c2.x = __uint_as_float(f2tf32(a2.x)); c2.y = __uint_as_float(f2tf32(a2.y));
        c2.z = __uint_as_float(f2tf32(a2.z)); c2.w = __uint_as_float(f2tf32(a2.w));
        c3.x = __uint_as_float(f2tf32(a3.x)); c3.y = __uint_as_float(f2tf32(a3.y));
        c3.z = __uint_as_float(f2tf32(a3.z)); c3.w = __uint_as_float(f2tf32(a3.w));
        *(float4*)&As[(0 * 32 + nl) * 132 + lane * 4] = c0;
        *(float4*)&As[(1 * 32 + nl) * 132 + lane * 4] = c1;
        *(float4*)&As[(2 * 32 + nl) * 132 + lane * 4] = c2;
        *(float4*)&As[(3 * 32 + nl) * 132 + lane * 4] = c3;
        if (lane == 0) {
            dens[nl * 4 + 0] = dn.x; dens[nl * 4 + 1] = dn.y;
            dens[nl * 4 + 2] = dn.z; dens[nl * 4 + 3] = dn.w;
        }
    }
    __syncthreads();

    // ---- phase 2: per-head GEMM ----
    int wn = wid & 3;
    int wm = wid >> 2;
    int rowHalf = wm & 1;
    int colHalf = wm >> 1;
    float acc[4][4];
#pragma unroll
    for (int nt = 0; nt < 4; nt++)
#pragma unroll
        for (int r = 0; r < 4; r++) acc[nt][r] = 0.f;

    for (int kc = 0; kc < 4; kc++) {
#pragma unroll
        for (int i = 0; i < 4; i++) {
            int id = tid + i * 512;
            int kr = id >> 6, cq = id & 63;
            float4 v = *(const float4*)&W1[(size_t)(kc * 32 + kr) * 256 + cq * 4];
            Bs[kr * 260 + cq * 4 + 0] = __uint_as_float(f2tf32(v.x));
            Bs[kr * 260 + cq * 4 + 1] = __uint_as_float(f2tf32(v.y));
            Bs[kr * 260 + cq * 4 + 2] = __uint_as_float(f2tf32(v.z));
            Bs[kr * 260 + cq * 4 + 3] = __uint_as_float(f2tf32(v.w));
        }
        __syncthreads();
#pragma unroll
        for (int kk = 0; kk < 32; kk += 8) {
            int k0 = kc * 32 + kk;
            int ar = wn * 32 + rowHalf * 16 + (lane >> 2);
            unsigned a0 = __float_as_uint(As[ar * 132 + k0 + (lane & 3)]);
            unsigned a1 = __float_as_uint(As[(ar + 8) * 132 + k0 + (lane & 3)]);
            unsigned a2 = __float_as_uint(As[ar * 132 + k0 + 4 + (lane & 3)]);
            unsigned a3 = __float_as_uint(As[(ar + 8) * 132 + k0 + 4 + (lane & 3)]);
#pragma unroll
            for (int nt = 0; nt < 4; nt++) {
                int cb = wn * 64 + colHalf * 32 + nt * 8 + (lane >> 2);
                unsigned b0 = __float_as_uint(Bs[(kk + (lane & 3)) * 260 + cb]);
                unsigned b1v = __float_as_uint(Bs[(kk + 4 + (lane & 3)) * 260 + cb]);
                mma_tf32(acc[nt][0], acc[nt][1], acc[nt][2], acc[nt][3],
                         a0, a1, a2, a3, b0, b1v);
            }
        }
        __syncthreads();
    }

    // ---- epilogue ----
#pragma unroll
    for (int nt = 0; nt < 4; nt++) {
        int col = wn * 64 + colHalf * 32 + nt * 8 + 2 * (lane & 3);
        float bb0 = b1[col], bb1 = b1[col + 1];
#pragma unroll
        for (int half = 0; half < 2; half++) {
            int r = rowHalf * 16 + (lane >> 2) + half * 8;
            int node = node0 + r;
            if (node < NN) {
                float inv = 1.0f / (dens[r * 4 + wn] + 1e-16f);
                float v0 = fmaxf(acc[nt][half * 2 + 0] * inv + bb0, 0.f);
                float v1 = fmaxf(acc[nt][half * 2 + 1] * inv + bb1, 0.f);
                *(float2*)&g_out1[(size_t)node * 256 + col] = make_float2(v0, v1);
            }
        }
    }
}

// ============ K4: g2 = out1 @ W2 (tf32) + fused alpha2 logits ============
__global__ void __launch_bounds__(256) gemm2_alpha2(const float* __restrict__ W2,
                                                    const float* __restrict__ a2s,
                                                    const float* __restrict__ a2d) {
    __shared__ float As[128][36];
    __shared__ float Bs2[32][72];
    __shared__ float sred[128][2];
    int tid = threadIdx.x, lane = tid & 31, wid = tid >> 5;
    int wm = wid >> 1, wn = wid & 1;
    int br = blockIdx.x * 128;
    if (tid < 128) { sred[tid][0] = 0.f; sred[tid][1] = 0.f; }

    float acc[2][4][4];
#pragma unroll
    for (int mt = 0; mt < 2; mt++)
#pragma unroll
        for (int nt = 0; nt < 4; nt++)
#pragma unroll
            for (int r = 0; r < 4; r++) acc[mt][nt][r] = 0.f;

    for (int k0 = 0; k0 < 256; k0 += 32) {
#pragma unroll
        for (int i = 0; i < 4; i++) {
            int id = tid + i * 256;
            int row = id >> 3, kq = id & 7;
            int gr = br + row;
            float4 v = make_float4(0,0,0,0);
            if (gr < NN) v = *(const float4*)&g_out1[(size_t)gr * 256 + k0 + kq * 4];
            As[row][kq * 4 + 0] = __uint_as_float(f2tf32(v.x));
            As[row][kq * 4 + 1] = __uint_as_float(f2tf32(v.y));
            As[row][kq * 4 + 2] = __uint_as_float(f2tf32(v.z));
            As[row][kq * 4 + 3] = __uint_as_float(f2tf32(v.w));
        }
#pragma unroll
        for (int i = 0; i < 2; i++) {
            int id = tid + i * 256;
            int kr = id >> 4, cq = id & 15;
            float4 v = *(const float4*)&W2[(size_t)(k0 + kr) * 64 + cq * 4];
            Bs2[kr][cq * 4 + 0] = __uint_as_float(f2tf32(v.x));
            Bs2[kr][cq * 4 + 1] = __uint_as_float(f2tf32(v.y));
            Bs2[kr][cq * 4 + 2] = __uint_as_float(f2tf32(v.z));
            Bs2[kr][cq * 4 + 3] = __uint_as_float(f2tf32(v.w));
        }
        __syncthreads();
#pragma unroll
        for (int kk = 0; kk < 32; kk += 8) {
            unsigned af[2][4];
#pragma unroll
            for (int mt = 0; mt < 2; mt++) {
                int rb = wm * 32 + mt * 16 + (lane >> 2);
                af[mt][0] = __float_as_uint(As[rb][kk + (lane & 3)]);
                af[mt][1] = __float_as_uint(As[rb + 8][kk + (lane & 3)]);
                af[mt][2] = __float_as_uint(As[rb][kk + 4 + (lane & 3)]);
                af[mt][3] = __float_as_uint(As[rb + 8][kk + 4 + (lane & 3)]);
            }
            unsigned bf[4][2];
#pragma unroll
            for (int nt = 0; nt < 4; nt++) {
                int cb = wn * 32 + nt * 8 + (lane >> 2);
                bf[nt][0] = __float_as_uint(Bs2[kk + (lane & 3)][cb]);
                bf[nt][1] = __float_as_uint(Bs2[kk + 4 + (lane & 3)][cb]);
            }
#pragma unroll
            for (int mt = 0; mt < 2; mt++)
#pragma unroll
                for (int nt = 0; nt < 4; nt++)
                    mma_tf32(acc[mt][nt][0], acc[mt][nt][1], acc[mt][nt][2], acc[mt][nt][3],
                             af[mt][0], af[mt][1], af[mt][2], af[mt][3],
                             bf[nt][0], bf[nt][1]);
        }
        __syncthreads();
    }

#pragma unroll
    for (int mt = 0; mt < 2; mt++) {
#pragma unroll
        for (int half = 0; half < 2; half++) {
            int rl = wm * 32 + mt * 16 + (lane >> 2) + half * 8;
            int row = br + rl;
            float ss = 0.f, sd = 0.f;
            if (row < NN) {
#pragma unroll
                for (int nt = 0; nt < 4; nt++) {
                    int col = wn * 32 + nt * 8 + 2 * (lane & 3);
                    float v0 = acc[mt][nt][half * 2 + 0];
                    float v1 = acc[mt][nt][half * 2 + 1];
                    *(float2*)&g_g2[(size_t)row * 64 + col] = make_float2(v0, v1);
                    ss += v0 * a2s[col] + v1 * a2s[col + 1];
                    sd += v0 * a2d[col] + v1 * a2d[col + 1];
                }
                atomicAdd(&sred[rl][0], ss);
                atomicAdd(&sred[rl][1], sd);
            }
        }
    }
    __syncthreads();
    if (tid < 128) {
        int row = br + tid;
        if (row < NN) {
            g_asrc2[row] = sred[tid][0];
            g_adst2[row] = sred[tid][1];
        }
    }
}

// ============ K5: layer2 gather-aggregate + norm/bias/relu + FC ============
__global__ void __launch_bounds__(256) aggr2_fc(const float* __restrict__ b2,
                                                const float* __restrict__ Wfc,
                                                const float* __restrict__ bfc,
                                                float* __restrict__ out) {
    __shared__ float wf[64 * ACT];
    for (int i = threadIdx.x; i < 64 * ACT; i += blockDim.x)
        wf[i] = Wfc[i];
    __syncthreads();
    int node = blockIdx.x * 8 + (threadIdx.x >> 5);
    int lane = threadIdx.x & 31;
    if (node >= NN) return;
    float ad = g_adst2[node];
    int s0 = g_off[node], s1 = g_off[node + 1];
    float2 acc = make_float2(0.f, 0.f);
    float den = 0.f;
    int i = s0;
    for (; i + 3 < s1; i += 4) {
        int sa = g_csr[i], sb = g_csr[i + 1], sc = g_csr[i + 2], sd = g_csr[i + 3];
        float la = g_asrc2[sa], lb = g_asrc2[sb], lc = g_asrc2[sc], ld = g_asrc2[sd];
        float2 va = *(const float2*)&g_g2[(size_t)sa * 64 + lane * 2];
        float2 vb = *(const float2*)&g_g2[(size_t)sb * 64 + lane * 2];
        float2 vc = *(const float2*)&g_g2[(size_t)sc * 64 + lane * 2];
        float2 vd = *(const float2*)&g_g2[(size_t)sd * 64 + lane * 2];
        float pa = __expf(lrelu(la + ad));
        float pb = __expf(lrelu(lb + ad));
        float pc = __expf(lrelu(lc + ad));
        float pd = __expf(lrelu(ld + ad));
        acc.x += pa * va.x + pb * vb.x + pc * vc.x + pd * vd.x;
        acc.y += pa * va.y + pb * vb.y + pc * vc.y + pd * vd.y;
        den += pa + pb + pc + pd;
    }
    for (; i < s1; i++) {
        int sa = g_csr[i];
        float pa = __expf(lrelu(g_asrc2[sa] + ad));
        float2 va = *(const float2*)&g_g2[(size_t)sa * 64 + lane * 2];
        acc.x += pa * va.x;
        acc.y += pa * va.y;
        den += pa;
    }
    float inv = 1.0f / (den + 1e-16f);
    float2 bb = *(const float2*)&b2[lane * 2];
    float ox = fmaxf(acc.x * inv + bb.x, 0.f);
    float oy = fmaxf(acc.y * inv + bb.y, 0.f);
    float fa[ACT];
#pragma unroll
    for (int a = 0; a < ACT; a++)
        fa[a] = ox * wf[(2 * lane) * ACT + a] + oy * wf[(2 * lane + 1) * ACT + a];
#pragma unroll
    for (int a = 0; a < ACT; a++) {
#pragma unroll
        for (int o = 16; o > 0; o >>= 1)
            fa[a] += __shfl_down_sync(~0u, fa[a], o);
    }
    if (lane == 0) {
#pragma unroll
        for (int a = 0; a < ACT; a++)
            out[node * ACT + a] = fa[a] + bfc[a];
    }
}

// ---------------- launch ----------------
extern "C" void kernel_launch(void* const* d_in, const int* in_sizes, int n_in,
                              void* d_out, int out_size) {
    const float* x      = (const float*)d_in[0];
    const int*   ei     = (const int*)  d_in[1];
    const float* W1     = (const float*)d_in[2];
    const float* a1_src = (const float*)d_in[3];
    const float* a1_dst = (const float*)d_in[4];
    const float* b1     = (const float*)d_in[5];
    const float* W2     = (const float*)d_in[6];
    const float* a2_src = (const float*)d_in[7];
    const float* a2_dst = (const float*)d_in[8];
    const float* b2     = (const float*)d_in[9];
    const float* Wfc    = (const float*)d_in[10];
    const float* bfc    = (const float*)d_in[11];
    float* out = (float*)d_out;

    int E = in_sizes[1] / 2;
    int histB = (E + 255) / 256;

    cudaFuncSetAttribute(layer1_fused, cudaFuncAttributeMaxDynamicSharedMemorySize, L1_SMEM);

    // 0: histogram + w1a precompute
    hist_wpre<<<histB + 4, 256>>>(ei, E, histB, W1, a1_src, a1_dst);
    // 1: scan + alpha1
    scan_alpha<<<1 + (NN + 31) / 32, 1024>>>(x);
    // 2: scatter + softmax weights
    scatter_p<<<(E + NN + 255) / 256, 256>>>(ei, E);
    // 3: fused gather + GEMM1 + epilogue   (<- profiled launch)
    layer1_fused<<<(NN + 31) / 32, 512, L1_SMEM>>>(x, W1, b1);
    // 4: GEMM2 + alpha2
    gemm2_alpha2<<<(NN + 127) / 128, 256>>>(W2, a2_src, a2_dst);
    // 5: layer2 aggregate + FC
    aggr2_fc<<<(NN + 7) / 8, 256>>>(b2, Wfc, bfc, out);
}